// round 12
// baseline (speedup 1.0000x reference)
#include <cuda_runtime.h>
#include <cuda_bf16.h>
#include <cstdint>
#include <math.h>

// ============================================================================
// AdaptiveLoss, bf16 mma.sync. Round 12:
//  - ONE fused GEMM launch (proj -> head-LSE -> clusters) with bid-ordered
//    soft dependencies (proj completion counters + spin).
//  - de-staged LSE epilogue: per-(row, 64col) partials straight to global;
//    zero epilogue syncs / smem staging.
//  - 2 CTAs/SM (256 thr, 128x128 tile, 32x64 warp tile), 3-stage cp.async.
// ============================================================================

#define B_ROWS 1024
#define ROWB   144
#define ACHUNK 18432            // 128 rows * 144B
#define BSTREAM 55296           // stream: B bufs at 3*ACHUNK
#define SMEM_SZ 110592          // 6 chunks

// 64-col partial chunks (2 per 128-col ytile): head 158, c0 158, c1 314,
// c2 626, c3 314
__device__ const int d_chunks[5] = {158, 158, 314, 626, 314};
__device__ const int d_pbase[5]  = {0, 161792, 323584, 645120, 1286144};
#define PM_TOTAL 1607680

__device__ float g_pm[PM_TOTAL];
__device__ float g_ps[PM_TOTAL];
__device__ float g_lse[5 * B_ROWS];
__device__ float g_tail[B_ROWS * 4];
__device__ float g_num[B_ROWS];
__device__ float g_den[B_ROWS];
__device__ int   g_flags[2];
__device__ int   g_done[4];     // proj completion counters (h0..h3)

__device__ __nv_bfloat16 bf_feat[B_ROWS * 1024];
__device__ __nv_bfloat16 bf_headW[10244096];
__device__ __nv_bfloat16 bf_out0[5120000];
__device__ __nv_bfloat16 bf_out1[5120000];
__device__ __nv_bfloat16 bf_out2[5120000];
__device__ __nv_bfloat16 bf_out3[1280000];
__device__ __nv_bfloat16 bf_proj0[512 * 1024];
__device__ __nv_bfloat16 bf_proj1[256 * 1024];
__device__ __nv_bfloat16 bf_proj2[128 * 1024];
__device__ __nv_bfloat16 bf_proj3[64 * 1024];
__device__ __nv_bfloat16 bf_h0[B_ROWS * 512];
__device__ __nv_bfloat16 bf_h1[B_ROWS * 256];
__device__ __nv_bfloat16 bf_h2[B_ROWS * 128];
__device__ __nv_bfloat16 bf_h3[B_ROWS * 64];

// ---------------------------------------------------------------- PTX helpers
__device__ __forceinline__ uint32_t smem_u32(const void* p) {
    uint32_t a;
    asm("{ .reg .u64 t; cvta.to.shared.u64 t, %1; cvt.u32.u64 %0, t; }"
        : "=r"(a) : "l"(p));
    return a;
}
__device__ __forceinline__ void cp16(uint32_t dst, const void* src) {
    asm volatile("cp.async.cg.shared.global [%0], [%1], 16;"
                 :: "r"(dst), "l"(src) : "memory");
}
__device__ __forceinline__ void cp16p(uint32_t dst, const void* src, int szbytes) {
    asm volatile("cp.async.cg.shared.global [%0], [%1], 16, %2;"
                 :: "r"(dst), "l"(src), "r"(szbytes) : "memory");
}
#define CP_COMMIT() asm volatile("cp.async.commit_group;" ::: "memory")
#define CP_WAIT1()  asm volatile("cp.async.wait_group 1;" ::: "memory")

__device__ __forceinline__ void ldsm_x4(uint32_t* r, uint32_t addr) {
    asm volatile("ldmatrix.sync.aligned.m8n8.x4.shared.b16 {%0,%1,%2,%3}, [%4];"
                 : "=r"(r[0]), "=r"(r[1]), "=r"(r[2]), "=r"(r[3]) : "r"(addr));
}
__device__ __forceinline__ void mma_bf16(float* c, const uint32_t* a,
                                         const uint32_t* b) {
    asm volatile(
        "mma.sync.aligned.m16n8k16.row.col.f32.bf16.bf16.f32 "
        "{%0,%1,%2,%3}, {%4,%5,%6,%7}, {%8,%9}, {%0,%1,%2,%3};"
        : "+f"(c[0]), "+f"(c[1]), "+f"(c[2]), "+f"(c[3])
        : "r"(a[0]), "r"(a[1]), "r"(a[2]), "r"(a[3]), "r"(b[0]), "r"(b[1]));
}

// ---- 32x64 warp-tile compute over one 64-K chunk ---------------------------
__device__ __forceinline__ void mma_tile(uint32_t aB, uint32_t bB,
    uint32_t aRowOff, uint32_t bRowOff, int warpN, float (&acc)[2][8][4])
{
#pragma unroll
    for (int ks = 0; ks < 4; ks++) {
        uint32_t af[2][4], bf4[4][4];
#pragma unroll
        for (int mt = 0; mt < 2; mt++)
            ldsm_x4(af[mt], aB + aRowOff + mt * (16 * ROWB) + ks * 32);
#pragma unroll
        for (int p = 0; p < 4; p++)
            ldsm_x4(bf4[p], bB + (warpN * 64 + p * 16) * ROWB + bRowOff + ks * 32);
#pragma unroll
        for (int mt = 0; mt < 2; mt++)
#pragma unroll
            for (int nt = 0; nt < 8; nt++)
                mma_bf16(acc[mt][nt], af[mt], &bf4[nt >> 1][(nt & 1) * 2]);
    }
}

// ---- de-staged online-LSE epilogue: per-(row, 64col half) -> global --------
// index within row: ytile*2 + warpN.  No syncs, no smem.
template <bool FULL>
__device__ __forceinline__ void epi_lse(float (&acc)[2][8][4], int N,
    int rowBase, int colBase, int sel, int ytile,
    int warpM, int warpN, int lane)
{
    const int chunks = d_chunks[sel];
    const size_t rowStride = (size_t)chunks;
    const int cidx = ytile * 2 + warpN;
#pragma unroll
    for (int mt = 0; mt < 2; mt++)
#pragma unroll
        for (int hf = 0; hf < 2; hf++) {
            const int rl = warpM * 32 + mt * 16 + (lane >> 2) + hf * 8;
            const int rg = rowBase + rl;
            float m = -INFINITY, s = 0.f;
            if (FULL) {
#pragma unroll
                for (int nt = 0; nt < 8; nt++)
#pragma unroll
                    for (int b2 = 0; b2 < 2; b2++)
                        m = fmaxf(m, acc[mt][nt][hf * 2 + b2]);
#pragma unroll
                for (int nt = 0; nt < 8; nt++)
#pragma unroll
                    for (int b2 = 0; b2 < 2; b2++)
                        s += __expf(acc[mt][nt][hf * 2 + b2] - m);
            } else {
#pragma unroll
                for (int nt = 0; nt < 8; nt++)
#pragma unroll
                    for (int b2 = 0; b2 < 2; b2++) {
                        const int cc = colBase + warpN * 64 + nt * 8
                                     + (lane & 3) * 2 + b2;
                        if (cc < N) m = fmaxf(m, acc[mt][nt][hf * 2 + b2]);
                    }
                if (m > -INFINITY) {
#pragma unroll
                    for (int nt = 0; nt < 8; nt++)
#pragma unroll
                        for (int b2 = 0; b2 < 2; b2++) {
                            const int cc = colBase + warpN * 64 + nt * 8
                                         + (lane & 3) * 2 + b2;
                            if (cc < N) {
                                const float v = acc[mt][nt][hf * 2 + b2];
                                s += __expf(v - m);
                                if (sel == 0 && cc >= 10000)
                                    g_tail[rg * 4 + (cc - 10000)] = v;
                            }
                        }
                }
            }
#pragma unroll
            for (int o = 1; o <= 2; o <<= 1) {
                const float mo = __shfl_xor_sync(0xffffffffu, m, o);
                const float so = __shfl_xor_sync(0xffffffffu, s, o);
                const float M2 = fmaxf(m, mo);
                if (M2 == -INFINITY) { m = M2; s = 0.f; }
                else { s = s * __expf(m - M2) + so * __expf(mo - M2); m = M2; }
            }
            if ((lane & 3) == 0) {
                const size_t o = d_pbase[sel] + (size_t)rg * rowStride + cidx;
                g_pm[o] = m; g_ps[o] = s;
            }
        }
}

// ============================================================================
// Streaming GEMM: 3-stage pipeline.  K>=256 (nch>=4).
// MODE 0: write bf16 C.  MODE 1: de-staged LSE epilogue.
// ============================================================================
template <int MODE, bool FULL>
__device__ __forceinline__ void gemm_stream(
    const __nv_bfloat16* __restrict__ A, const __nv_bfloat16* __restrict__ W,
    __nv_bfloat16* __restrict__ Cb, int N, int K,
    int rowBase, int colBase, int sel, int ytile, char* smem)
{
    const uint32_t sb = smem_u32(smem);
    const int tid = threadIdx.x, lane = tid & 31, wid = tid >> 5;
    const int warpM = wid & 3, warpN = wid >> 2;

    float acc[2][8][4];
#pragma unroll
    for (int i = 0; i < 2; i++)
#pragma unroll
        for (int j = 0; j < 8; j++)
#pragma unroll
            for (int k = 0; k < 4; k++) acc[i][j][k] = 0.f;

    const uint32_t aRowOff =
        (uint32_t)((warpM * 32 + ((lane >> 3) & 1) * 8 + (lane & 7)) * ROWB
                   + (lane >> 4) * 16);
    const uint32_t bRowOff =
        (uint32_t)((((lane >> 4) & 1) * 8 + (lane & 7)) * ROWB
                   + ((lane >> 3) & 1) * 16);

    auto load_chunk = [&](int c, int buf) {
        const int k0 = c * 64;
        const uint32_t aB = sb + buf * ACHUNK;
        const uint32_t bB = sb + BSTREAM + buf * ACHUNK;
#pragma unroll
        for (int i = 0; i < 4; i++) {                 // A: 1024 units
            const int t = tid + i * 256, r = t >> 3, q = t & 7;
            cp16(aB + r * ROWB + q * 16,
                 A + (size_t)(rowBase + r) * K + k0 + q * 8);
        }
#pragma unroll
        for (int i = 0; i < 4; i++) {                 // B: 1024 units
            const int t = tid + i * 256, r = t >> 3, q = t & 7;
            if (FULL) {
                cp16(bB + r * ROWB + q * 16,
                     W + (size_t)(colBase + r) * K + k0 + q * 8);
            } else {
                const int n = colBase + r;
                const int ok = (n < N) ? 16 : 0;
                cp16p(bB + r * ROWB + q * 16,
                      W + (size_t)(ok ? n : 0) * K + k0 + q * 8, ok);
            }
        }
    };

    const int nch = K >> 6;
    load_chunk(0, 0);
    CP_COMMIT();
    load_chunk(1, 1);
    CP_COMMIT();
    int buf = 0, nbuf = 2;
    for (int c = 0; c < nch; c++) {
        CP_WAIT1();
        __syncthreads();
        if (c + 2 < nch) { load_chunk(c + 2, nbuf); }
        CP_COMMIT();
        mma_tile(sb + buf * ACHUNK, sb + BSTREAM + buf * ACHUNK,
                 aRowOff, bRowOff, warpN, acc);
        buf = (buf == 2) ? 0 : buf + 1;
        nbuf = (nbuf == 2) ? 0 : nbuf + 1;
    }

    if (MODE == 0) {
        __syncthreads();
#pragma unroll
        for (int mt = 0; mt < 2; mt++)
#pragma unroll
            for (int nt = 0; nt < 8; nt++)
#pragma unroll
                for (int rg = 0; rg < 4; rg++) {
                    const int r = rowBase + warpM * 32 + mt * 16 + (lane >> 2)
                                + (rg >> 1) * 8;
                    const int cc = colBase + warpN * 64 + nt * 8
                                 + (lane & 3) * 2 + (rg & 1);
                    if (cc < N)
                        Cb[(size_t)r * N + cc] = __float2bfloat16(acc[mt][nt][rg]);
                }
    } else {
        epi_lse<FULL>(acc, N, rowBase, colBase, sel, ytile,
                      warpM, warpN, lane);
    }
}

// ============================================================================
// A-resident GEMM (K<=128): A loaded once; streams B for `cnt` consecutive
// 128-col ytiles (3 B buffers).
// ============================================================================
template <int NCH>
__device__ __forceinline__ void gemm_resident(
    const __nv_bfloat16* __restrict__ A, const __nv_bfloat16* __restrict__ W,
    int N, int rowBase, int y0, int cnt, int sel, char* smem)
{
    const uint32_t sb = smem_u32(smem);
    const int tid = threadIdx.x, lane = tid & 31, wid = tid >> 5;
    const int warpM = wid & 3, warpN = wid >> 2;
    const int K = NCH * 64;

    const uint32_t aRowOff =
        (uint32_t)((warpM * 32 + ((lane >> 3) & 1) * 8 + (lane & 7)) * ROWB
                   + (lane >> 4) * 16);
    const uint32_t bRowOff =
        (uint32_t)((((lane >> 4) & 1) * 8 + (lane & 7)) * ROWB
                   + ((lane >> 3) & 1) * 16);

#pragma unroll
    for (int u = tid; u < NCH * 1024; u += 256) {
        const int c = u >> 10, t = u & 1023, r = t >> 3, q = t & 7;
        cp16(sb + c * ACHUNK + r * ROWB + q * 16,
             A + (size_t)(rowBase + r) * K + c * 64 + q * 8);
    }

    auto load_b = [&](int i, int buf) {
        const int t = i / NCH, c = i - t * NCH;
        const int colBase = (y0 + t) * 128;
        const int k0 = c * 64;
        const uint32_t bB = sb + NCH * ACHUNK + buf * ACHUNK;
        if (colBase + 128 <= N) {
#pragma unroll
            for (int j = 0; j < 4; j++) {
                const int tt = tid + j * 256, r = tt >> 3, q = tt & 7;
                cp16(bB + r * ROWB + q * 16,
                     W + (size_t)(colBase + r) * K + k0 + q * 8);
            }
        } else {
#pragma unroll
            for (int j = 0; j < 4; j++) {
                const int tt = tid + j * 256, r = tt >> 3, q = tt & 7;
                const int n = colBase + r;
                const int ok = (n < N) ? 16 : 0;
                cp16p(bB + r * ROWB + q * 16,
                      W + (size_t)(ok ? n : 0) * K + k0 + q * 8, ok);
            }
        }
    };

    const int total = cnt * NCH;
    load_b(0, 0);
    CP_COMMIT();
    if (total > 1) load_b(1, 1);
    CP_COMMIT();

    float acc[2][8][4];
#pragma unroll
    for (int i = 0; i < 2; i++)
#pragma unroll
        for (int j = 0; j < 8; j++)
#pragma unroll
            for (int k = 0; k < 4; k++) acc[i][j][k] = 0.f;

    int buf = 0, nbuf = 2;
    for (int i = 0; i < total; i++) {
        const int t = i / NCH, c = i - t * NCH;
        CP_WAIT1();
        __syncthreads();
        if (i + 2 < total) { load_b(i + 2, nbuf); }
        CP_COMMIT();
        mma_tile(sb + c * ACHUNK, sb + NCH * ACHUNK + buf * ACHUNK,
                 aRowOff, bRowOff, warpN, acc);
        buf = (buf == 2) ? 0 : buf + 1;
        nbuf = (nbuf == 2) ? 0 : nbuf + 1;
        if (c == NCH - 1) {
            const int colBase = (y0 + t) * 128;
            if (colBase + 128 <= N)
                epi_lse<true>(acc, N, rowBase, colBase, sel, y0 + t,
                              warpM, warpN, lane);
            else
                epi_lse<false>(acc, N, rowBase, colBase, sel, y0 + t,
                               warpM, warpN, lane);
#pragma unroll
            for (int a = 0; a < 2; a++)
#pragma unroll
                for (int b = 0; b < 8; b++)
#pragma unroll
                    for (int k = 0; k < 4; k++) acc[a][b][k] = 0.f;
        }
    }
}

// ---- wait for proj producers of h_i ----------------------------------------
__device__ __forceinline__ void wait_done(int m, int need) {
    if (threadIdx.x == 0) {
        while (((volatile int*)g_done)[m] < need) __nanosleep(200);
    }
    __syncthreads();
    __threadfence();
}

// ============================================================================
// ONE fused GEMM launch, 3376 blocks (1-D, bid-ordered deps):
//  [0,64)       proj   (p=bid>>3: 0-3 proj0 | 4-5 proj1 | 6 proj2 | 7 proj3)
//  [64,696)     head LSE (79 ytiles x 8)
//  [696,1328)   c0 K=512 stream  (79 x 8)   waits g_done[0]==32
//  [1328,2584)  c1 K=256 stream  (157 x 8)  waits g_done[1]==16
//  [2584,3216)  c2 K=128 resident(79 grp x 8) waits g_done[2]==8
//  [3216,3376)  c3 K=64  resident(20 grp x 8) waits g_done[3]==8
// ============================================================================
__global__ __launch_bounds__(256, 2)
void gemm_all_kernel()
{
    extern __shared__ char smem[];
    const int id = blockIdx.x;
    if (id < 64) {
        const int t = id >> 3, rb = (id & 7) * 128;
        const __nv_bfloat16* W; __nv_bfloat16* Cb;
        int N, colBase, sel;
        if (t < 4)      { W = bf_proj0; Cb = bf_h0; N = 512; colBase = t * 128; sel = 0; }
        else if (t < 6) { W = bf_proj1; Cb = bf_h1; N = 256; colBase = (t - 4) * 128; sel = 1; }
        else if (t == 6){ W = bf_proj2; Cb = bf_h2; N = 128; colBase = 0; sel = 2; }
        else            { W = bf_proj3; Cb = bf_h3; N = 64;  colBase = 0; sel = 3; }
        if (colBase + 128 <= N)
            gemm_stream<0, true>(bf_feat, W, Cb, N, 1024, rb, colBase, -1, 0, smem);
        else
            gemm_stream<0, false>(bf_feat, W, Cb, N, 1024, rb, colBase, -1, 0, smem);
        __threadfence();
        __syncthreads();
        if (threadIdx.x == 0) atomicAdd(&g_done[sel], 1);
    } else if (id < 696) {
        const int u = id - 64, yt = u >> 3, rb = (u & 7) * 128;
        if (yt < 78)
            gemm_stream<1, true>(bf_feat, bf_headW, nullptr, 10004, 1024,
                                 rb, yt * 128, 0, yt, smem);
        else
            gemm_stream<1, false>(bf_feat, bf_headW, nullptr, 10004, 1024,
                                  rb, yt * 128, 0, yt, smem);
    } else if (id < 1328) {
        const int u = id - 696, yt = u >> 3, rb = (u & 7) * 128;
        wait_done(0, 32);
        if (yt < 78)
            gemm_stream<1, true>(bf_h0, bf_out0, nullptr, 10000, 512,
                                 rb, yt * 128, 1, yt, smem);
        else
            gemm_stream<1, false>(bf_h0, bf_out0, nullptr, 10000, 512,
                                  rb, yt * 128, 1, yt, smem);
    } else if (id < 2584) {
        const int u = id - 1328, yt = u >> 3, rb = (u & 7) * 128;
        wait_done(1, 16);
        if (yt < 156)
            gemm_stream<1, true>(bf_h1, bf_out1, nullptr, 20000, 256,
                                 rb, yt * 128, 2, yt, smem);
        else
            gemm_stream<1, false>(bf_h1, bf_out1, nullptr, 20000, 256,
                                  rb, yt * 128, 2, yt, smem);
    } else if (id < 3216) {
        const int u = id - 2584, yg = u >> 3, rb = (u & 7) * 128;
        wait_done(2, 8);
        const int y0 = yg * 4, cnt = (313 - y0 < 4) ? (313 - y0) : 4;
        gemm_resident<2>(bf_h2, bf_out2, 40000, rb, y0, cnt, 3, smem);
    } else {
        const int u = id - 3216, yg = u >> 3, rb = (u & 7) * 128;
        wait_done(3, 8);
        const int y0 = yg * 8, cnt = (157 - y0 < 8) ? (157 - y0) : 8;
        gemm_resident<1>(bf_h3, bf_out3, 20000, rb, y0, cnt, 4, smem);
    }
}

// ---------------------------------------------------------------- cvt (fused)
__global__ void cvt_all(const float* s0, const float* s1, const float* s2,
                        const float* s3, const float* s4, const float* s5,
                        const float* s6, const float* s7, const float* s8,
                        const float* s9)
{
    const int cum[11] = {0, 262144, 2823168, 4103168, 5383168, 6663168,
                         6983168, 7114240, 7179776, 7212544, 7228928};
    for (int i = blockIdx.x * blockDim.x + threadIdx.x; i < 7228928;
         i += gridDim.x * blockDim.x) {
        int seg = 0;
#pragma unroll
        for (int t = 1; t < 10; t++) seg += (i >= cum[t]);
        const int off = i - cum[seg];
        const float* src;
        __nv_bfloat16* dst;
        switch (seg) {
            case 0: src = s0; dst = bf_feat;  break;
            case 1: src = s1; dst = bf_headW; break;
            case 2: src = s2; dst = bf_out0;  break;
            case 3: src = s3; dst = bf_out1;  break;
            case 4: src = s4; dst = bf_out2;  break;
            case 5: src = s5; dst = bf_out3;  break;
            case 6: src = s6; dst = bf_proj0; break;
            case 7: src = s7; dst = bf_proj1; break;
            case 8: src = s8; dst = bf_proj2; break;
            default: src = s9; dst = bf_proj3; break;
        }
        const float4 v = ((const float4*)src)[off];
        __nv_bfloat162* p = (__nv_bfloat162*)dst + off * 2;
        p[0] = __floats2bfloat162_rn(v.x, v.y);
        p[1] = __floats2bfloat162_rn(v.z, v.w);
    }
}

// ---------------------------------------------------------------- small kernels
__global__ void init_kernel(const void* tgt, const void* msk) {
    const int tid = threadIdx.x;
    if (tid < B_ROWS) { g_num[tid] = 0.f; g_den[tid] = 0.f; }
    if (tid < 4) g_done[tid] = 0;
    if (tid == 0) {
        const int* ti = (const int*)tgt;
        int nz = 0;
        for (int j = 0; j < 128; j++) nz += (ti[2 * j + 1] != 0);
        g_flags[0] = (nz <= 8) ? 1 : 0;
        const unsigned int* mw = (const unsigned int*)msk;
        int looks_i32 = 1;
        for (int j = 0; j < 64; j++) if (mw[j] > 255u) looks_i32 = 0;
        g_flags[1] = looks_i32;
    }
}

__global__ void combine_kernel() {
    int row = blockIdx.x, mat = blockIdx.y, lane = threadIdx.x;
    int chunks = d_chunks[mat];
    const float* pm = g_pm + d_pbase[mat] + (size_t)row * chunks;
    const float* ps = g_ps + d_pbase[mat] + (size_t)row * chunks;
    float m = -INFINITY, s = 0.f;
    for (int c = lane; c < chunks; c += 32) {
        float mo = pm[c], so = ps[c];
        float M2 = fmaxf(m, mo);
        if (M2 == -INFINITY) { m = M2; s = 0.f; }
        else { s = s * __expf(m - M2) + so * __expf(mo - M2); m = M2; }
    }
    for (int o = 1; o < 32; o <<= 1) {
        float mo = __shfl_xor_sync(0xffffffffu, m, o);
        float so = __shfl_xor_sync(0xffffffffu, s, o);
        float M2 = fmaxf(m, mo);
        if (M2 == -INFINITY) { m = M2; s = 0.f; }
        else { s = s * __expf(m - M2) + so * __expf(mo - M2); m = M2; }
    }
    if (lane == 0) g_lse[mat * B_ROWS + row] = m + logf(s);
}

// warp per target; bf16 operands (L2-warm), fp32 accumulate
__global__ void loss_kernel(const float* __restrict__ discard,
                            const void* __restrict__ tgt,
                            const void* __restrict__ msk)
{
    int gwarp = (blockIdx.x * blockDim.x + threadIdx.x) >> 5;
    int lane  = threadIdx.x & 31;
    if (gwarp >= B_ROWS * 128) return;
    int b = gwarp >> 7;

    long long v;
    if (g_flags[0]) v = ((const long long*)tgt)[gwarp];
    else            v = (long long)((const int*)tgt)[gwarp];

    float mk;
    if (g_flags[1]) mk = (((const int*)msk)[gwarp] != 0) ? 1.f : 0.f;
    else            mk = (((const unsigned char*)msk)[gwarp] != 0) ? 1.f : 0.f;

    const __nv_bfloat16 *a, *w;
    int Kd; float lse, extra;
    float hlse = g_lse[b];
    if (v < 10000) {
        a = bf_feat + (size_t)b * 1024; w = bf_headW + (size_t)v * 1024;
        Kd = 1024; lse = hlse; extra = 0.f;
    } else if (v < 20000) {
        a = bf_h0 + (size_t)b * 512; w = bf_out0 + (size_t)(v - 10000) * 512;
        Kd = 512; lse = g_lse[1 * B_ROWS + b]; extra = g_tail[b * 4 + 0] - hlse;
    } else if (v < 40000) {
        a = bf_h1 + (size_t)b * 256; w = bf_out1 + (size_t)(v - 20000) * 256;
        Kd = 256; lse = g_lse[2 * B_ROWS + b]; extra = g_tail[b * 4 + 1] - hlse;
    } else if (v < 80000) {
        a = bf_h2 + (size_t)b * 128; w = bf_out2 + (size_t)(v - 40000) * 128;
        Kd = 128; lse = g_lse[3 * B_ROWS + b]; extra = g_tail[b * 4 + 2] - hlse;
    } else {
        a = bf_h3 + (size_t)b * 64; w = bf_out3 + (size_t)(v - 80000) * 64;
        Kd = 64; lse = g_lse[4 * B_ROWS + b]; extra = g_tail[b * 4 + 3] - hlse;
    }

    float dot = 0.f;
    for (int k = lane * 8; k < Kd; k += 256) {
        const uint4 av = *(const uint4*)(a + k);
        const uint4 wv = *(const uint4*)(w + k);
        const uint32_t aw[4] = {av.x, av.y, av.z, av.w};
        const uint32_t ww[4] = {wv.x, wv.y, wv.z, wv.w};
#pragma unroll
        for (int j = 0; j < 4; j++) {
            const float2 af2 = __bfloat1622float2(*(const __nv_bfloat162*)&aw[j]);
            const float2 wf2 = __bfloat1622float2(*(const __nv_bfloat162*)&ww[j]);
            dot += af2.x * wf2.x + af2.y * wf2.y;
        }
    }
#pragma unroll
    for (int o = 16; o >= 1; o >>= 1) dot += __shfl_xor_sync(0xffffffffu, dot, o);

    if (lane == 0) {
        float lp = dot - lse + extra;
        float wt = (1.f - discard[v]) * mk;
        atomicAdd(&g_num[b], -lp * wt);
        atomicAdd(&g_den[b], wt);
    }
}

__global__ void final_kernel(float* out) {
    __shared__ float red[256];
    float s = 0.f;
    for (int i = threadIdx.x; i < B_ROWS; i += 256) s += g_num[i] / g_den[i];
    red[threadIdx.x] = s;
    __syncthreads();
    for (int o = 128; o >= 1; o >>= 1) {
        if (threadIdx.x < o) red[threadIdx.x] += red[threadIdx.x + o];
        __syncthreads();
    }
    if (threadIdx.x == 0)
        out[0] = (float)((double)red[0] / (1024.0 + 1e-5));
}

// ============================================================================
extern "C" void kernel_launch(void* const* d_in, const int* in_sizes, int n_in,
                              void* d_out, int out_size)
{
    const float* feat    = (const float*)d_in[0];
    const float* headW   = (const float*)d_in[1];
    const float* proj0   = (const float*)d_in[2];
    const float* out0    = (const float*)d_in[3];
    const float* proj1   = (const float*)d_in[4];
    const float* out1    = (const float*)d_in[5];
    const float* proj2   = (const float*)d_in[6];
    const float* out2    = (const float*)d_in[7];
    const float* proj3   = (const float*)d_in[8];
    const float* out3    = (const float*)d_in[9];
    const float* discard = (const float*)d_in[10];
    const void*  tgt     = d_in[11];
    const void*  msk     = d_in[12];
    float* out = (float*)d_out;

    cudaFuncSetAttribute(gemm_all_kernel,
                         cudaFuncAttributeMaxDynamicSharedMemorySize, SMEM_SZ);

    init_kernel<<<1, 1024>>>(tgt, msk);
    cvt_all<<<4096, 256>>>(feat, headW, out0, out1, out2, out3,
                           proj0, proj1, proj2, proj3);
    gemm_all_kernel<<<3376, 256, SMEM_SZ>>>();
    combine_kernel<<<dim3(1024, 5), 32>>>();
    loss_kernel<<<16384, 256>>>(discard, tgt, msk);
    final_kernel<<<1, 256>>>(out);
}

// round 15
// speedup vs baseline: 1.1283x; 1.1283x over previous
#include <cuda_runtime.h>
#include <cuda_bf16.h>
#include <cstdint>
#include <math.h>

// ============================================================================
// AdaptiveLoss, bf16 mma.sync. Round 13:
//  - ALL GEMM operands pre-packed into tile-major 16KB chunk images
//    (128 rows x 128B, XOR swizzle (q*16)^((r&7)<<4) -> ldsm conflict-free)
//  - mainloop loads chunks via cp.async.bulk + mbarrier (1 instr vs 1024)
//  - 2 CTAs/SM (256 thr, 128x128 tile, 32x64 warp tile), 3-stage pipeline
//  - de-staged LSE epilogue, R11 two-launch structure
// ============================================================================

#define B_ROWS 1024
#define IMG    16384u           // one chunk image: 128 rows x 128 B
#define STG    32768u           // stream stage: A img + B img
#define MB_OFF 98304u
#define SMEM_SZ 98368u

// 64-col partial chunks (2 per 128-col ytile)
__device__ const int d_chunks[5] = {158, 158, 314, 626, 314};
__device__ const int d_pbase[5]  = {0, 161792, 323584, 645120, 1286144};
#define PM_TOTAL 1607680

__device__ float g_pm[PM_TOTAL];
__device__ float g_ps[PM_TOTAL];
__device__ float g_lse[5 * B_ROWS];
__device__ float g_tail[B_ROWS * 4];
__device__ float g_num[B_ROWS];
__device__ float g_den[B_ROWS];
__device__ int   g_flags[2];

// packed operand storage (uint4 = 16B units; 1024 units per image)
__device__ uint4 pk_feat [131072];    // 8 rowblk x 16 ch
__device__ uint4 pk_headW[1294336];   // 79 tiles x 16 ch
__device__ uint4 pk_out0 [647168];    // 79 x 8
__device__ uint4 pk_out1 [643072];    // 157 x 4
__device__ uint4 pk_out2 [641024];    // 313 x 2
__device__ uint4 pk_out3 [160768];    // 157 x 1
__device__ uint4 pk_proj0[65536];     // 4 x 16
__device__ uint4 pk_proj1[32768];     // 2 x 16
__device__ uint4 pk_proj2[16384];     // 1 x 16
__device__ uint4 pk_proj3[16384];     // 1 x 16
__device__ uint4 pk_h0   [65536];     // 8 rowblk x 8 ch   (K=512)
__device__ uint4 pk_h1   [32768];     // 8 x 4             (K=256)
__device__ uint4 pk_h2   [16384];     // 8 x 2             (K=128)
__device__ uint4 pk_h3   [8192];      // 8 x 1             (K=64)

// ---------------------------------------------------------------- PTX helpers
__device__ __forceinline__ uint32_t smem_u32(const void* p) {
    uint32_t a;
    asm("{ .reg .u64 t; cvta.to.shared.u64 t, %1; cvt.u32.u64 %0, t; }"
        : "=r"(a) : "l"(p));
    return a;
}
#define MBAR_INIT(a, c) \
    asm volatile("mbarrier.init.shared.b64 [%0], %1;" :: "r"(a), "r"(c) : "memory")
#define MBAR_EXPECT(a, b) \
    asm volatile("mbarrier.arrive.expect_tx.shared.b64 _, [%0], %1;" \
                 :: "r"(a), "r"(b) : "memory")
#define MBAR_WAIT(addr, par) do {                                            \
    uint32_t _m = (addr), _p = (par), _d;                                    \
    asm volatile("{\n\t.reg .pred p;\n\t"                                    \
        "mbarrier.try_wait.parity.shared.b64 p, [%1], %2;\n\t"               \
        "selp.b32 %0, 1, 0, p;\n\t}" : "=r"(_d) : "r"(_m), "r"(_p) : "memory"); \
    while (!_d) {                                                            \
        asm volatile("{\n\t.reg .pred p;\n\t"                                \
            "mbarrier.try_wait.parity.shared.b64 p, [%1], %2;\n\t"           \
            "selp.b32 %0, 1, 0, p;\n\t}" : "=r"(_d) : "r"(_m), "r"(_p) : "memory"); \
    }                                                                        \
} while (0)
__device__ __forceinline__ void bulk_cp(uint32_t dst, const void* src,
                                        uint32_t bytes, uint32_t mbar) {
    asm volatile(
        "cp.async.bulk.shared::cta.global.mbarrier::complete_tx::bytes "
        "[%0], [%1], %2, [%3];"
        :: "r"(dst), "l"(src), "r"(bytes), "r"(mbar) : "memory");
}
__device__ __forceinline__ void ldsm_x4(uint32_t* r, uint32_t addr) {
    asm volatile("ldmatrix.sync.aligned.m8n8.x4.shared.b16 {%0,%1,%2,%3}, [%4];"
                 : "=r"(r[0]), "=r"(r[1]), "=r"(r[2]), "=r"(r[3]) : "r"(addr));
}
__device__ __forceinline__ void mma_bf16(float* c, const uint32_t* a,
                                         const uint32_t* b) {
    asm volatile(
        "mma.sync.aligned.m16n8k16.row.col.f32.bf16.bf16.f32 "
        "{%0,%1,%2,%3}, {%4,%5,%6,%7}, {%8,%9}, {%0,%1,%2,%3};"
        : "+f"(c[0]), "+f"(c[1]), "+f"(c[2]), "+f"(c[3])
        : "r"(a[0]), "r"(a[1]), "r"(a[2]), "r"(a[3]), "r"(b[0]), "r"(b[1]));
}

// ---- 32x64 warp-tile compute over one 64-K chunk (packed layout) -----------
// addr(row, quad) = row*128 + (quad*16 ^ ((row&7)<<4)); row&7 == lane&7 here.
__device__ __forceinline__ void mma_tile(uint32_t aB, uint32_t bB,
    uint32_t aRow0, uint32_t bRow0, uint32_t xm,
    uint32_t aqs, uint32_t bqs, float (&acc)[2][8][4])
{
#pragma unroll
    for (int ks = 0; ks < 4; ks++) {
        uint32_t af[2][4], bf4[4][4];
        const uint32_t aoff = ((uint32_t)(ks * 32) + aqs) ^ xm;
        const uint32_t boff = ((uint32_t)(ks * 32) + bqs) ^ xm;
#pragma unroll
        for (int mt = 0; mt < 2; mt++)
            ldsm_x4(af[mt], aB + aRow0 + mt * 2048 + aoff);
#pragma unroll
        for (int p = 0; p < 4; p++)
            ldsm_x4(bf4[p], bB + bRow0 + p * 2048 + boff);
#pragma unroll
        for (int mt = 0; mt < 2; mt++)
#pragma unroll
            for (int nt = 0; nt < 8; nt++)
                mma_bf16(acc[mt][nt], af[mt], &bf4[nt >> 1][(nt & 1) * 2]);
    }
}

// ---- de-staged online-LSE epilogue -----------------------------------------
template <bool FULL>
__device__ __forceinline__ void epi_lse(float (&acc)[2][8][4], int N,
    int rowBase, int colBase, int sel, int ytile,
    int warpM, int warpN, int lane)
{
    const int chunks = d_chunks[sel];
    const int cidx = ytile * 2 + warpN;
#pragma unroll
    for (int mt = 0; mt < 2; mt++)
#pragma unroll
        for (int hf = 0; hf < 2; hf++) {
            const int rg = rowBase + warpM * 32 + mt * 16 + (lane >> 2) + hf * 8;
            float m = -INFINITY, s = 0.f;
            if (FULL) {
#pragma unroll
                for (int nt = 0; nt < 8; nt++)
#pragma unroll
                    for (int b2 = 0; b2 < 2; b2++)
                        m = fmaxf(m, acc[mt][nt][hf * 2 + b2]);
#pragma unroll
                for (int nt = 0; nt < 8; nt++)
#pragma unroll
                    for (int b2 = 0; b2 < 2; b2++)
                        s += __expf(acc[mt][nt][hf * 2 + b2] - m);
            } else {
#pragma unroll
                for (int nt = 0; nt < 8; nt++)
#pragma unroll
                    for (int b2 = 0; b2 < 2; b2++) {
                        const int cc = colBase + warpN * 64 + nt * 8
                                     + (lane & 3) * 2 + b2;
                        if (cc < N) m = fmaxf(m, acc[mt][nt][hf * 2 + b2]);
                    }
                if (m > -INFINITY) {
#pragma unroll
                    for (int nt = 0; nt < 8; nt++)
#pragma unroll
                        for (int b2 = 0; b2 < 2; b2++) {
                            const int cc = colBase + warpN * 64 + nt * 8
                                         + (lane & 3) * 2 + b2;
                            if (cc < N) {
                                const float v = acc[mt][nt][hf * 2 + b2];
                                s += __expf(v - m);
                                if (sel == 0 && cc >= 10000)
                                    g_tail[rg * 4 + (cc - 10000)] = v;
                            }
                        }
                }
            }
#pragma unroll
            for (int o = 1; o <= 2; o <<= 1) {
                const float mo = __shfl_xor_sync(0xffffffffu, m, o);
                const float so = __shfl_xor_sync(0xffffffffu, s, o);
                const float M2 = fmaxf(m, mo);
                if (M2 == -INFINITY) { m = M2; s = 0.f; }
                else { s = s * __expf(m - M2) + so * __expf(mo - M2); m = M2; }
            }
            if ((lane & 3) == 0) {
                const size_t o = d_pbase[sel] + (size_t)rg * chunks + cidx;
                g_pm[o] = m; g_ps[o] = s;
            }
        }
}

// ============================================================================
// Streaming GEMM over packed images: one bulk copy pair per chunk.
// MODE 0: pack C into Cpk (packed h layout, Kh = N).  MODE 1: LSE epilogue.
// ============================================================================
template <int MODE, bool FULL>
__device__ __forceinline__ void gemm_stream(
    const uint4* __restrict__ Apk, const uint4* __restrict__ Bpk,
    uint4* __restrict__ Cpk, int N, int K,
    int rowBase, int colBase, int sel, int ytile, char* smem)
{
    const uint32_t sb = smem_u32(smem);
    const int tid = threadIdx.x, lane = tid & 31, wid = tid >> 5;
    const int warpM = wid & 3, warpN = wid >> 2;
    const int nch = K >> 6;

    const uint4* Aimg = Apk + (size_t)(rowBase >> 7) * nch * 1024;
    const uint4* Bimg = Bpk + (size_t)(colBase >> 7) * nch * 1024;

    if (tid == 0) {
        MBAR_INIT(sb + MB_OFF + 0, 1);
        MBAR_INIT(sb + MB_OFF + 8, 1);
        MBAR_INIT(sb + MB_OFF + 16, 1);
    }
    __syncthreads();
    if (tid == 0) {
        MBAR_EXPECT(sb + MB_OFF, 2 * IMG);
        bulk_cp(sb, Aimg, IMG, sb + MB_OFF);
        bulk_cp(sb + IMG, Bimg, IMG, sb + MB_OFF);
        MBAR_EXPECT(sb + MB_OFF + 8, 2 * IMG);
        bulk_cp(sb + STG, Aimg + 1024, IMG, sb + MB_OFF + 8);
        bulk_cp(sb + STG + IMG, Bimg + 1024, IMG, sb + MB_OFF + 8);
    }

    float acc[2][8][4];
#pragma unroll
    for (int i = 0; i < 2; i++)
#pragma unroll
        for (int j = 0; j < 8; j++)
#pragma unroll
            for (int k = 0; k < 4; k++) acc[i][j][k] = 0.f;

    const uint32_t xm = (uint32_t)((lane & 7) << 4);
    const uint32_t aRow0 =
        (uint32_t)((warpM * 32 + ((lane >> 3) & 1) * 8 + (lane & 7)) * 128);
    const uint32_t bRow0 =
        (uint32_t)((warpN * 64 + ((lane >> 4) & 1) * 8 + (lane & 7)) * 128);
    const uint32_t aqs = (uint32_t)((lane >> 4) * 16);
    const uint32_t bqs = (uint32_t)(((lane >> 3) & 1) * 16);

    for (int c = 0; c < nch; c++) {
        const int buf = c % 3;
        MBAR_WAIT(sb + MB_OFF + buf * 8, (c / 3) & 1);
        __syncthreads();
        if (tid == 0 && c + 2 < nch) {
            const int nb = (c + 2) % 3;
            MBAR_EXPECT(sb + MB_OFF + nb * 8, 2 * IMG);
            bulk_cp(sb + nb * STG, Aimg + (c + 2) * 1024, IMG,
                    sb + MB_OFF + nb * 8);
            bulk_cp(sb + nb * STG + IMG, Bimg + (c + 2) * 1024, IMG,
                    sb + MB_OFF + nb * 8);
        }
        mma_tile(sb + buf * STG, sb + buf * STG + IMG,
                 aRow0, bRow0, xm, aqs, bqs, acc);
    }

    if (MODE == 0) {
        // pack C into Cpk: element (r, cc) -> chunk (r>>7)*(N>>6)+(cc>>6)
        const int nchC = N >> 6;
        char* base = (char*)Cpk + (size_t)(rowBase >> 7) * nchC * IMG;
#pragma unroll
        for (int mt = 0; mt < 2; mt++)
#pragma unroll
            for (int nt = 0; nt < 8; nt++)
#pragma unroll
                for (int rg = 0; rg < 4; rg++) {
                    const int r = warpM * 32 + mt * 16 + (lane >> 2)
                                + (rg >> 1) * 8;
                    const int cc = colBase + warpN * 64 + nt * 8
                                 + (lane & 3) * 2 + (rg & 1);
                    if (cc < N) {
                        const size_t off = (size_t)(cc >> 6) * IMG
                            + (uint32_t)(r * 128)
                            + ((((cc >> 3) & 7) * 16) ^ ((r & 7) << 4))
                            + (cc & 7) * 2;
                        *(__nv_bfloat16*)(base + off) =
                            __float2bfloat16(acc[mt][nt][rg]);
                    }
                }
    } else {
        epi_lse<FULL>(acc, N, rowBase, colBase, sel, ytile, warpM, warpN, lane);
    }
}

// ============================================================================
// A-resident GEMM (K<=128): A images loaded once; streams B images for `cnt`
// consecutive 128-col ytiles.  B stages at 49152 + s*IMG.
// ============================================================================
template <int NCH>
__device__ __forceinline__ void gemm_resident(
    const uint4* __restrict__ Apk, const uint4* __restrict__ Bpk,
    int N, int rowBase, int y0, int cnt, int sel, char* smem)
{
    const uint32_t sb = smem_u32(smem);
    const int tid = threadIdx.x, lane = tid & 31, wid = tid >> 5;
    const int warpM = wid & 3, warpN = wid >> 2;

    const uint4* Aimg = Apk + (size_t)(rowBase >> 7) * NCH * 1024;

    if (tid == 0) {
        MBAR_INIT(sb + MB_OFF + 0, 1);
        MBAR_INIT(sb + MB_OFF + 8, 1);
        MBAR_INIT(sb + MB_OFF + 16, 1);
    }
    __syncthreads();
    const int total = cnt * NCH;
    if (tid == 0) {
        MBAR_EXPECT(sb + MB_OFF, (NCH + 1) * IMG);
#pragma unroll
        for (int c = 0; c < NCH; c++)
            bulk_cp(sb + c * IMG, Aimg + c * 1024, IMG, sb + MB_OFF);
        bulk_cp(sb + 49152u, Bpk + (size_t)(y0 * NCH) * 1024, IMG, sb + MB_OFF);
        if (total > 1) {
            MBAR_EXPECT(sb + MB_OFF + 8, IMG);
            bulk_cp(sb + 49152u + IMG, Bpk + (size_t)(y0 * NCH + 1) * 1024,
                    IMG, sb + MB_OFF + 8);
        }
    }

    float acc[2][8][4];
#pragma unroll
    for (int i = 0; i < 2; i++)
#pragma unroll
        for (int j = 0; j < 8; j++)
#pragma unroll
            for (int k = 0; k < 4; k++) acc[i][j][k] = 0.f;

    const uint32_t xm = (uint32_t)((lane & 7) << 4);
    const uint32_t aRow0 =
        (uint32_t)((warpM * 32 + ((lane >> 3) & 1) * 8 + (lane & 7)) * 128);
    const uint32_t bRow0 =
        (uint32_t)((warpN * 64 + ((lane >> 4) & 1) * 8 + (lane & 7)) * 128);
    const uint32_t aqs = (uint32_t)((lane >> 4) * 16);
    const uint32_t bqs = (uint32_t)(((lane >> 3) & 1) * 16);

    for (int i = 0; i < total; i++) {
        const int t = i / NCH, c = i - t * NCH;
        const int buf = i % 3;
        MBAR_WAIT(sb + MB_OFF + buf * 8, (i / 3) & 1);
        __syncthreads();
        if (tid == 0 && i + 2 < total) {
            const int nb = (i + 2) % 3;
            MBAR_EXPECT(sb + MB_OFF + nb * 8, IMG);
            bulk_cp(sb + 49152u + nb * IMG,
                    Bpk + (size_t)(y0 * NCH + i + 2) * 1024, IMG,
                    sb + MB_OFF + nb * 8);
        }
        mma_tile(sb + c * IMG, sb + 49152u + buf * IMG,
                 aRow0, bRow0, xm, aqs, bqs, acc);
        if (c == NCH - 1) {
            const int colBase = (y0 + t) * 128;
            if (colBase + 128 <= N)
                epi_lse<true>(acc, N, rowBase, colBase, sel, y0 + t,
                              warpM, warpN, lane);
            else
                epi_lse<false>(acc, N, rowBase, colBase, sel, y0 + t,
                               warpM, warpN, lane);
#pragma unroll
            for (int a = 0; a < 2; a++)
#pragma unroll
                for (int b = 0; b < 8; b++)
#pragma unroll
                    for (int k = 0; k < 4; k++) acc[a][b][k] = 0.f;
        }
    }
}

// ============================================================================
// launch 2: head LSE (79 ytiles) + 8 proj tiles.  grid (8, 87)
// ============================================================================
__global__ __launch_bounds__(256, 2)
void head_proj_kernel()
{
    extern __shared__ char smem[];
    const int y = blockIdx.y;
    const int rowBase = blockIdx.x * 128;
    if (y < 78) {
        gemm_stream<1, true>(pk_feat, pk_headW, nullptr, 10004, 1024,
                             rowBase, y * 128, 0, y, smem);
    } else if (y == 78) {
        gemm_stream<1, false>(pk_feat, pk_headW, nullptr, 10004, 1024,
                              rowBase, y * 128, 0, y, smem);
    } else {
        const uint4* W; uint4* C; int N, colBase;
        if (y < 83)      { W = pk_proj0; C = pk_h0; N = 512; colBase = (y - 79) * 128; }
        else if (y < 85) { W = pk_proj1; C = pk_h1; N = 256; colBase = (y - 83) * 128; }
        else if (y == 85){ W = pk_proj2; C = pk_h2; N = 128; colBase = 0; }
        else             { W = pk_proj3; C = pk_h3; N = 64;  colBase = 0; }
        if (colBase + 128 <= N)
            gemm_stream<0, true>(pk_feat, W, C, N, 1024, rowBase, colBase,
                                 -1, 0, smem);
        else
            gemm_stream<0, false>(pk_feat, W, C, N, 1024, rowBase, colBase,
                                  -1, 0, smem);
    }
}

// ============================================================================
// launch 3: clusters.  grid (8, 335)
// ============================================================================
__global__ __launch_bounds__(256, 2)
void cluster_kernel()
{
    extern __shared__ char smem[];
    const int y = blockIdx.y;
    const int rowBase = blockIdx.x * 128;
    if (y < 79) {
        if (y < 78)
            gemm_stream<1, true>(pk_h0, pk_out0, nullptr, 10000, 512,
                                 rowBase, y * 128, 1, y, smem);
        else
            gemm_stream<1, false>(pk_h0, pk_out0, nullptr, 10000, 512,
                                  rowBase, y * 128, 1, y, smem);
    } else if (y < 236) {
        const int yt = y - 79;
        if (yt < 156)
            gemm_stream<1, true>(pk_h1, pk_out1, nullptr, 20000, 256,
                                 rowBase, yt * 128, 2, yt, smem);
        else
            gemm_stream<1, false>(pk_h1, pk_out1, nullptr, 20000, 256,
                                  rowBase, yt * 128, 2, yt, smem);
    } else if (y < 315) {
        const int y0 = (y - 236) * 4;
        const int cnt = (313 - y0 < 4) ? (313 - y0) : 4;
        gemm_resident<2>(pk_h2, pk_out2, 40000, rowBase, y0, cnt, 3, smem);
    } else {
        const int y0 = (y - 315) * 8;
        const int cnt = (157 - y0 < 8) ? (157 - y0) : 8;
        gemm_resident<1>(pk_h3, pk_out3, 20000, rowBase, y0, cnt, 4, smem);
    }
}

// ============================================================================
// pack_all: fp32 -> packed bf16 chunk images.  One block per 16KB image.
// ============================================================================
__global__ void pack_all(const float* s0, const float* s1, const float* s2,
                         const float* s3, const float* s4, const float* s5,
                         const float* s6, const float* s7, const float* s8,
                         const float* s9)
{
    int id = blockIdx.x;
    const float* src; uint4* dst; int K, N;
    if (id < 128)       { src = s0; dst = pk_feat;  K = 1024; N = 1024; }
    else if (id < 1392) { src = s1; dst = pk_headW; K = 1024; N = 10004; id -= 128; }
    else if (id < 2024) { src = s2; dst = pk_out0;  K = 512;  N = 10000; id -= 1392; }
    else if (id < 2652) { src = s3; dst = pk_out1;  K = 256;  N = 20000; id -= 2024; }
    else if (id < 3278) { src = s4; dst = pk_out2;  K = 128;  N = 40000; id -= 2652; }
    else if (id < 3435) { src = s5; dst = pk_out3;  K = 64;   N = 20000; id -= 3278; }
    else if (id < 3499) { src = s6; dst = pk_proj0; K = 1024; N = 512;  id -= 3435; }
    else if (id < 3531) { src = s7; dst = pk_proj1; K = 1024; N = 256;  id -= 3499; }
    else if (id < 3547) { src = s8; dst = pk_proj2; K = 1024; N = 128;  id -= 3531; }
    else                { src = s9; dst = pk_proj3; K = 1024; N = 64;   id -= 3547; }

    const int nch = K >> 6;
    const int t = id / nch, c = id - t * nch;
    char* img = (char*)(dst + (size_t)id * 1024);

    for (int u = threadIdx.x; u < 2048; u += 256) {
        const int r = u >> 4, half = u & 15, q = half >> 1, lo = half & 1;
        const int n = t * 128 + r;
        float4 v = make_float4(0.f, 0.f, 0.f, 0.f);
        if (n < N)
            v = *(const float4*)(src + (size_t)n * K + c * 64 + q * 8 + lo * 4);
        const uint32_t boff = (uint32_t)(r * 128)
                            + (((uint32_t)(q * 16)) ^ ((uint32_t)((r & 7) << 4)))
                            + lo * 8;
        __nv_bfloat162 p0 = __floats2bfloat162_rn(v.x, v.y);
        __nv_bfloat162 p1 = __floats2bfloat162_rn(v.z, v.w);
        uint2 w;
        w.x = *(uint32_t*)&p0; w.y = *(uint32_t*)&p1;
        *(uint2*)(img + boff) = w;
    }
}

// ---------------------------------------------------------------- small kernels
__global__ void init_kernel(const void* tgt, const void* msk) {
    const int tid = threadIdx.x;
    if (tid < B_ROWS) { g_num[tid] = 0.f; g_den[tid] = 0.f; }
    if (tid == 0) {
        const int* ti = (const int*)tgt;
        int nz = 0;
        for (int j = 0; j < 128; j++) nz += (ti[2 * j + 1] != 0);
        g_flags[0] = (nz <= 8) ? 1 : 0;
        const unsigned int* mw = (const unsigned int*)msk;
        int looks_i32 = 1;
        for (int j = 0; j < 64; j++) if (mw[j] > 255u) looks_i32 = 0;
        g_flags[1] = looks_i32;
    }
}

__global__ void combine_kernel() {
    int row = blockIdx.x, mat = blockIdx.y, lane = threadIdx.x;
    int chunks = d_chunks[mat];
    const float* pm = g_pm + d_pbase[mat] + (size_t)row * chunks;
    const float* ps = g_ps + d_pbase[mat] + (size_t)row * chunks;
    float m = -INFINITY, s = 0.f;
    for (int c = lane; c < chunks; c += 32) {
        float mo = pm[c], so = ps[c];
        float M2 = fmaxf(m, mo);
        if (M2 == -INFINITY) { m = M2; s = 0.f; }
        else { s = s * __expf(m - M2) + so * __expf(mo - M2); m = M2; }
    }
    for (int o = 1; o < 32; o <<= 1) {
        float mo = __shfl_xor_sync(0xffffffffu, m, o);
        float so = __shfl_xor_sync(0xffffffffu, s, o);
        float M2 = fmaxf(m, mo);
        if (M2 == -INFINITY) { m = M2; s = 0.f; }
        else { s = s * __expf(m - M2) + so * __expf(mo - M2); m = M2; }
    }
    if (lane == 0) g_lse[mat * B_ROWS + row] = m + logf(s);
}

// warp per target; packed bf16 operands, fp32 accumulate
__global__ void loss_kernel(const float* __restrict__ discard,
                            const void* __restrict__ tgt,
                            const void* __restrict__ msk)
{
    int gwarp = (blockIdx.x * blockDim.x + threadIdx.x) >> 5;
    int lane  = threadIdx.x & 31;
    if (gwarp >= B_ROWS * 128) return;
    int b = gwarp >> 7;

    long long v;
    if (g_flags[0]) v = ((const long long*)tgt)[gwarp];
    else            v = (long long)((const int*)tgt)[gwarp];

    float mk;
    if (g_flags[1]) mk = (((const int*)msk)[gwarp] != 0) ? 1.f : 0.f;
    else            mk = (((const unsigned char*)msk)[gwarp] != 0) ? 1.f : 0.f;

    const uint4 *A, *W;
    int arow, wrow, Kd; float lse, extra;
    float hlse = g_lse[b];
    if (v < 10000) {
        A = pk_feat; arow = b; W = pk_headW; wrow = (int)v;
        Kd = 1024; lse = hlse; extra = 0.f;
    } else if (v < 20000) {
        A = pk_h0; arow = b; W = pk_out0; wrow = (int)v - 10000;
        Kd = 512; lse = g_lse[1 * B_ROWS + b]; extra = g_tail[b * 4 + 0] - hlse;
    } else if (v < 40000) {
        A = pk_h1; arow = b; W = pk_out1; wrow = (int)v - 20000;
        Kd = 256; lse = g_lse[2 * B_ROWS + b]; extra = g_tail[b * 4 + 1] - hlse;
    } else if (v < 80000) {
        A = pk_h2; arow = b; W = pk_out2; wrow = (int)v - 40000;
        Kd = 128; lse = g_lse[3 * B_ROWS + b]; extra = g_tail[b * 4 + 2] - hlse;
    } else {
        A = pk_h3; arow = b; W = pk_out3; wrow = (int)v - 80000;
        Kd = 64; lse = g_lse[4 * B_ROWS + b]; extra = g_tail[b * 4 + 3] - hlse;
    }

    const int nch = Kd >> 6;
    const uint4* abase = A + (size_t)(arow >> 7) * nch * 1024;
    const uint4* wbase = W + (size_t)(wrow >> 7) * nch * 1024;
    const int ar = arow & 127, wr = wrow & 127;
    const uint32_t q16x = (uint32_t)((lane & 7) * 16);
    const uint32_t aidx0 = ((uint32_t)(ar * 128)
                           + (q16x ^ ((uint32_t)((ar & 7) << 4)))) >> 4;
    const uint32_t widx0 = ((uint32_t)(wr * 128)
                           + (q16x ^ ((uint32_t)((wr & 7) << 4)))) >> 4;

    float dot = 0.f;
    for (int k = lane * 8; k < Kd; k += 256) {
        const int c = k >> 6;
        const uint4 av = abase[c * 1024 + aidx0];
        const uint4 wv = wbase[c * 1024 + widx0];
        const uint32_t aw[4] = {av.x, av.y, av.z, av.w};
        const uint32_t ww[4] = {wv.x, wv.y, wv.z, wv.w};
#pragma unroll
        for (int j = 0; j < 4; j++) {
            const float2 af2 = __bfloat1622float2(*(const __nv_bfloat162*)&aw[j]);
            const float2 wf2 = __bfloat1622float2(*(const __nv_bfloat162*)&ww[j]);
            dot += af2.x * wf2.x + af2.y * wf2.y;
        }
    }
#pragma unroll
    for (int o = 16; o >= 1; o >>= 1) dot += __shfl_xor_sync(0xffffffffu, dot, o);

    if (lane == 0) {
        float lp = dot - lse + extra;
        float wt = (1.f - discard[v]) * mk;
        atomicAdd(&g_num[b], -lp * wt);
        atomicAdd(&g_den[b], wt);
    }
}

__global__ void final_kernel(float* out) {
    __shared__ float red[256];
    float s = 0.f;
    for (int i = threadIdx.x; i < B_ROWS; i += 256) s += g_num[i] / g_den[i];
    red[threadIdx.x] = s;
    __syncthreads();
    for (int o = 128; o >= 1; o >>= 1) {
        if (threadIdx.x < o) red[threadIdx.x] += red[threadIdx.x + o];
        __syncthreads();
    }
    if (threadIdx.x == 0)
        out[0] = (float)((double)red[0] / (1024.0 + 1e-5));
}

// ============================================================================
extern "C" void kernel_launch(void* const* d_in, const int* in_sizes, int n_in,
                              void* d_out, int out_size)
{
    const float* feat    = (const float*)d_in[0];
    const float* headW   = (const float*)d_in[1];
    const float* proj0   = (const float*)d_in[2];
    const float* out0    = (const float*)d_in[3];
    const float* proj1   = (const float*)d_in[4];
    const float* out1    = (const float*)d_in[5];
    const float* proj2   = (const float*)d_in[6];
    const float* out2    = (const float*)d_in[7];
    const float* proj3   = (const float*)d_in[8];
    const float* out3    = (const float*)d_in[9];
    const float* discard = (const float*)d_in[10];
    const void*  tgt     = d_in[11];
    const void*  msk     = d_in[12];
    float* out = (float*)d_out;

    cudaFuncSetAttribute(head_proj_kernel,
                         cudaFuncAttributeMaxDynamicSharedMemorySize, SMEM_SZ);
    cudaFuncSetAttribute(cluster_kernel,
                         cudaFuncAttributeMaxDynamicSharedMemorySize, SMEM_SZ);

    init_kernel<<<1, 1024>>>(tgt, msk);
    pack_all<<<3563, 256>>>(feat, headW, out0, out1, out2, out3,
                            proj0, proj1, proj2, proj3);
    head_proj_kernel<<<dim3(8, 87),  256, SMEM_SZ>>>();
    cluster_kernel<<<dim3(8, 335),   256, SMEM_SZ>>>();
    combine_kernel<<<dim3(1024, 5), 32>>>();
    loss_kernel<<<16384, 256>>>(discard, tgt, msk);
    final_kernel<<<1, 256>>>(out);
}

// round 16
// speedup vs baseline: 1.1376x; 1.0082x over previous
#include <cuda_runtime.h>
#include <cuda_bf16.h>
#include <cstdint>
#include <math.h>

// ============================================================================
// AdaptiveLoss, bf16 mma.sync. Round 16:
//  - R15 packed-image + cp.async.bulk GEMM core (unchanged arithmetic)
//  - proj split out; head-LSE runs on side stream CONCURRENT with clusters
//  - pack_all: one uint4 store per quad
//  - mbarrier waits with suspend hint
// ============================================================================

#define B_ROWS 1024
#define IMG    16384u           // one chunk image: 128 rows x 128 B
#define STG    32768u           // stream stage: A img + B img
#define MB_OFF 98304u
#define SMEM_SZ 98368u

// 64-col partial chunks (2 per 128-col ytile)
__device__ const int d_chunks[5] = {158, 158, 314, 626, 314};
__device__ const int d_pbase[5]  = {0, 161792, 323584, 645120, 1286144};
#define PM_TOTAL 1607680

__device__ float g_pm[PM_TOTAL];
__device__ float g_ps[PM_TOTAL];
__device__ float g_lse[5 * B_ROWS];
__device__ float g_tail[B_ROWS * 4];
__device__ float g_num[B_ROWS];
__device__ float g_den[B_ROWS];
__device__ int   g_flags[2];

// packed operand storage (uint4 = 16B units; 1024 units per image)
__device__ uint4 pk_feat [131072];
__device__ uint4 pk_headW[1294336];
__device__ uint4 pk_out0 [647168];
__device__ uint4 pk_out1 [643072];
__device__ uint4 pk_out2 [641024];
__device__ uint4 pk_out3 [160768];
__device__ uint4 pk_proj0[65536];
__device__ uint4 pk_proj1[32768];
__device__ uint4 pk_proj2[16384];
__device__ uint4 pk_proj3[16384];
__device__ uint4 pk_h0   [65536];
__device__ uint4 pk_h1   [32768];
__device__ uint4 pk_h2   [16384];
__device__ uint4 pk_h3   [8192];

// ---------------------------------------------------------------- PTX helpers
__device__ __forceinline__ uint32_t smem_u32(const void* p) {
    uint32_t a;
    asm("{ .reg .u64 t; cvta.to.shared.u64 t, %1; cvt.u32.u64 %0, t; }"
        : "=r"(a) : "l"(p));
    return a;
}
#define MBAR_INIT(a, c) \
    asm volatile("mbarrier.init.shared.b64 [%0], %1;" :: "r"(a), "r"(c) : "memory")
#define MBAR_EXPECT(a, b) \
    asm volatile("mbarrier.arrive.expect_tx.shared.b64 _, [%0], %1;" \
                 :: "r"(a), "r"(b) : "memory")
#define MBAR_WAIT(addr, par) do {                                            \
    uint32_t _m = (addr), _p = (par), _d;                                    \
    do {                                                                     \
        asm volatile("{\n\t.reg .pred p;\n\t"                                \
            "mbarrier.try_wait.parity.shared.b64 p, [%1], %2, 0x989680;\n\t" \
            "selp.b32 %0, 1, 0, p;\n\t}" : "=r"(_d) : "r"(_m), "r"(_p) : "memory"); \
    } while (!_d);                                                           \
} while (0)
__device__ __forceinline__ void bulk_cp(uint32_t dst, const void* src,
                                        uint32_t bytes, uint32_t mbar) {
    asm volatile(
        "cp.async.bulk.shared::cta.global.mbarrier::complete_tx::bytes "
        "[%0], [%1], %2, [%3];"
        :: "r"(dst), "l"(src), "r"(bytes), "r"(mbar) : "memory");
}
__device__ __forceinline__ void ldsm_x4(uint32_t* r, uint32_t addr) {
    asm volatile("ldmatrix.sync.aligned.m8n8.x4.shared.b16 {%0,%1,%2,%3}, [%4];"
                 : "=r"(r[0]), "=r"(r[1]), "=r"(r[2]), "=r"(r[3]) : "r"(addr));
}
__device__ __forceinline__ void mma_bf16(float* c, const uint32_t* a,
                                         const uint32_t* b) {
    asm volatile(
        "mma.sync.aligned.m16n8k16.row.col.f32.bf16.bf16.f32 "
        "{%0,%1,%2,%3}, {%4,%5,%6,%7}, {%8,%9}, {%0,%1,%2,%3};"
        : "+f"(c[0]), "+f"(c[1]), "+f"(c[2]), "+f"(c[3])
        : "r"(a[0]), "r"(a[1]), "r"(a[2]), "r"(a[3]), "r"(b[0]), "r"(b[1]));
}

// ---- 32x64 warp-tile compute over one 64-K chunk (packed layout) -----------
__device__ __forceinline__ void mma_tile(uint32_t aB, uint32_t bB,
    uint32_t aRow0, uint32_t bRow0, uint32_t xm,
    uint32_t aqs, uint32_t bqs, float (&acc)[2][8][4])
{
#pragma unroll
    for (int ks = 0; ks < 4; ks++) {
        uint32_t af[2][4], bf4[4][4];
        const uint32_t aoff = ((uint32_t)(ks * 32) + aqs) ^ xm;
        const uint32_t boff = ((uint32_t)(ks * 32) + bqs) ^ xm;
#pragma unroll
        for (int mt = 0; mt < 2; mt++)
            ldsm_x4(af[mt], aB + aRow0 + mt * 2048 + aoff);
#pragma unroll
        for (int p = 0; p < 4; p++)
            ldsm_x4(bf4[p], bB + bRow0 + p * 2048 + boff);
#pragma unroll
        for (int mt = 0; mt < 2; mt++)
#pragma unroll
            for (int nt = 0; nt < 8; nt++)
                mma_bf16(acc[mt][nt], af[mt], &bf4[nt >> 1][(nt & 1) * 2]);
    }
}

// ---- de-staged online-LSE epilogue -----------------------------------------
template <bool FULL>
__device__ __forceinline__ void epi_lse(float (&acc)[2][8][4], int N,
    int rowBase, int colBase, int sel, int ytile,
    int warpM, int warpN, int lane)
{
    const int chunks = d_chunks[sel];
    const int cidx = ytile * 2 + warpN;
#pragma unroll
    for (int mt = 0; mt < 2; mt++)
#pragma unroll
        for (int hf = 0; hf < 2; hf++) {
            const int rg = rowBase + warpM * 32 + mt * 16 + (lane >> 2) + hf * 8;
            float m = -INFINITY, s = 0.f;
            if (FULL) {
#pragma unroll
                for (int nt = 0; nt < 8; nt++)
#pragma unroll
                    for (int b2 = 0; b2 < 2; b2++)
                        m = fmaxf(m, acc[mt][nt][hf * 2 + b2]);
#pragma unroll
                for (int nt = 0; nt < 8; nt++)
#pragma unroll
                    for (int b2 = 0; b2 < 2; b2++)
                        s += __expf(acc[mt][nt][hf * 2 + b2] - m);
            } else {
#pragma unroll
                for (int nt = 0; nt < 8; nt++)
#pragma unroll
                    for (int b2 = 0; b2 < 2; b2++) {
                        const int cc = colBase + warpN * 64 + nt * 8
                                     + (lane & 3) * 2 + b2;
                        if (cc < N) m = fmaxf(m, acc[mt][nt][hf * 2 + b2]);
                    }
                if (m > -INFINITY) {
#pragma unroll
                    for (int nt = 0; nt < 8; nt++)
#pragma unroll
                        for (int b2 = 0; b2 < 2; b2++) {
                            const int cc = colBase + warpN * 64 + nt * 8
                                         + (lane & 3) * 2 + b2;
                            if (cc < N) {
                                const float v = acc[mt][nt][hf * 2 + b2];
                                s += __expf(v - m);
                                if (sel == 0 && cc >= 10000)
                                    g_tail[rg * 4 + (cc - 10000)] = v;
                            }
                        }
                }
            }
#pragma unroll
            for (int o = 1; o <= 2; o <<= 1) {
                const float mo = __shfl_xor_sync(0xffffffffu, m, o);
                const float so = __shfl_xor_sync(0xffffffffu, s, o);
                const float M2 = fmaxf(m, mo);
                if (M2 == -INFINITY) { m = M2; s = 0.f; }
                else { s = s * __expf(m - M2) + so * __expf(mo - M2); m = M2; }
            }
            if ((lane & 3) == 0) {
                const size_t o = d_pbase[sel] + (size_t)rg * chunks + cidx;
                g_pm[o] = m; g_ps[o] = s;
            }
        }
}

// ============================================================================
// Streaming GEMM over packed images: one bulk copy pair per chunk.
// ============================================================================
template <int MODE, bool FULL>
__device__ __forceinline__ void gemm_stream(
    const uint4* __restrict__ Apk, const uint4* __restrict__ Bpk,
    uint4* __restrict__ Cpk, int N, int K,
    int rowBase, int colBase, int sel, int ytile, char* smem)
{
    const uint32_t sb = smem_u32(smem);
    const int tid = threadIdx.x, lane = tid & 31, wid = tid >> 5;
    const int warpM = wid & 3, warpN = wid >> 2;
    const int nch = K >> 6;

    const uint4* Aimg = Apk + (size_t)(rowBase >> 7) * nch * 1024;
    const uint4* Bimg = Bpk + (size_t)(colBase >> 7) * nch * 1024;

    if (tid == 0) {
        MBAR_INIT(sb + MB_OFF + 0, 1);
        MBAR_INIT(sb + MB_OFF + 8, 1);
        MBAR_INIT(sb + MB_OFF + 16, 1);
    }
    __syncthreads();
    if (tid == 0) {
        MBAR_EXPECT(sb + MB_OFF, 2 * IMG);
        bulk_cp(sb, Aimg, IMG, sb + MB_OFF);
        bulk_cp(sb + IMG, Bimg, IMG, sb + MB_OFF);
        MBAR_EXPECT(sb + MB_OFF + 8, 2 * IMG);
        bulk_cp(sb + STG, Aimg + 1024, IMG, sb + MB_OFF + 8);
        bulk_cp(sb + STG + IMG, Bimg + 1024, IMG, sb + MB_OFF + 8);
    }

    float acc[2][8][4];
#pragma unroll
    for (int i = 0; i < 2; i++)
#pragma unroll
        for (int j = 0; j < 8; j++)
#pragma unroll
            for (int k = 0; k < 4; k++) acc[i][j][k] = 0.f;

    const uint32_t xm = (uint32_t)((lane & 7) << 4);
    const uint32_t aRow0 =
        (uint32_t)((warpM * 32 + ((lane >> 3) & 1) * 8 + (lane & 7)) * 128);
    const uint32_t bRow0 =
        (uint32_t)((warpN * 64 + ((lane >> 4) & 1) * 8 + (lane & 7)) * 128);
    const uint32_t aqs = (uint32_t)((lane >> 4) * 16);
    const uint32_t bqs = (uint32_t)(((lane >> 3) & 1) * 16);

    for (int c = 0; c < nch; c++) {
        const int buf = c % 3;
        MBAR_WAIT(sb + MB_OFF + buf * 8, (c / 3) & 1);
        __syncthreads();
        if (tid == 0 && c + 2 < nch) {
            const int nb = (c + 2) % 3;
            MBAR_EXPECT(sb + MB_OFF + nb * 8, 2 * IMG);
            bulk_cp(sb + nb * STG, Aimg + (c + 2) * 1024, IMG,
                    sb + MB_OFF + nb * 8);
            bulk_cp(sb + nb * STG + IMG, Bimg + (c + 2) * 1024, IMG,
                    sb + MB_OFF + nb * 8);
        }
        mma_tile(sb + buf * STG, sb + buf * STG + IMG,
                 aRow0, bRow0, xm, aqs, bqs, acc);
    }

    if (MODE == 0) {
        const int nchC = N >> 6;
        char* base = (char*)Cpk + (size_t)(rowBase >> 7) * nchC * IMG;
#pragma unroll
        for (int mt = 0; mt < 2; mt++)
#pragma unroll
            for (int nt = 0; nt < 8; nt++)
#pragma unroll
                for (int rg = 0; rg < 4; rg++) {
                    const int r = warpM * 32 + mt * 16 + (lane >> 2)
                                + (rg >> 1) * 8;
                    const int cc = colBase + warpN * 64 + nt * 8
                                 + (lane & 3) * 2 + (rg & 1);
                    if (cc < N) {
                        const size_t off = (size_t)(cc >> 6) * IMG
                            + (uint32_t)(r * 128)
                            + ((((cc >> 3) & 7) * 16) ^ ((r & 7) << 4))
                            + (cc & 7) * 2;
                        *(__nv_bfloat16*)(base + off) =
                            __float2bfloat16(acc[mt][nt][rg]);
                    }
                }
    } else {
        epi_lse<FULL>(acc, N, rowBase, colBase, sel, ytile, warpM, warpN, lane);
    }
}

// ============================================================================
// A-resident GEMM (K<=128)
// ============================================================================
template <int NCH>
__device__ __forceinline__ void gemm_resident(
    const uint4* __restrict__ Apk, const uint4* __restrict__ Bpk,
    int N, int rowBase, int y0, int cnt, int sel, char* smem)
{
    const uint32_t sb = smem_u32(smem);
    const int tid = threadIdx.x, lane = tid & 31, wid = tid >> 5;
    const int warpM = wid & 3, warpN = wid >> 2;

    const uint4* Aimg = Apk + (size_t)(rowBase >> 7) * NCH * 1024;

    if (tid == 0) {
        MBAR_INIT(sb + MB_OFF + 0, 1);
        MBAR_INIT(sb + MB_OFF + 8, 1);
        MBAR_INIT(sb + MB_OFF + 16, 1);
    }
    __syncthreads();
    const int total = cnt * NCH;
    if (tid == 0) {
        MBAR_EXPECT(sb + MB_OFF, (NCH + 1) * IMG);
#pragma unroll
        for (int c = 0; c < NCH; c++)
            bulk_cp(sb + c * IMG, Aimg + c * 1024, IMG, sb + MB_OFF);
        bulk_cp(sb + 49152u, Bpk + (size_t)(y0 * NCH) * 1024, IMG, sb + MB_OFF);
        if (total > 1) {
            MBAR_EXPECT(sb + MB_OFF + 8, IMG);
            bulk_cp(sb + 49152u + IMG, Bpk + (size_t)(y0 * NCH + 1) * 1024,
                    IMG, sb + MB_OFF + 8);
        }
    }

    float acc[2][8][4];
#pragma unroll
    for (int i = 0; i < 2; i++)
#pragma unroll
        for (int j = 0; j < 8; j++)
#pragma unroll
            for (int k = 0; k < 4; k++) acc[i][j][k] = 0.f;

    const uint32_t xm = (uint32_t)((lane & 7) << 4);
    const uint32_t aRow0 =
        (uint32_t)((warpM * 32 + ((lane >> 3) & 1) * 8 + (lane & 7)) * 128);
    const uint32_t bRow0 =
        (uint32_t)((warpN * 64 + ((lane >> 4) & 1) * 8 + (lane & 7)) * 128);
    const uint32_t aqs = (uint32_t)((lane >> 4) * 16);
    const uint32_t bqs = (uint32_t)(((lane >> 3) & 1) * 16);

    for (int i = 0; i < total; i++) {
        const int t = i / NCH, c = i - t * NCH;
        const int buf = i % 3;
        MBAR_WAIT(sb + MB_OFF + buf * 8, (i / 3) & 1);
        __syncthreads();
        if (tid == 0 && i + 2 < total) {
            const int nb = (i + 2) % 3;
            MBAR_EXPECT(sb + MB_OFF + nb * 8, IMG);
            bulk_cp(sb + 49152u + nb * IMG,
                    Bpk + (size_t)(y0 * NCH + i + 2) * 1024, IMG,
                    sb + MB_OFF + nb * 8);
        }
        mma_tile(sb + c * IMG, sb + 49152u + buf * IMG,
                 aRow0, bRow0, xm, aqs, bqs, acc);
        if (c == NCH - 1) {
            const int colBase = (y0 + t) * 128;
            if (colBase + 128 <= N)
                epi_lse<true>(acc, N, rowBase, colBase, sel, y0 + t,
                              warpM, warpN, lane);
            else
                epi_lse<false>(acc, N, rowBase, colBase, sel, y0 + t,
                               warpM, warpN, lane);
#pragma unroll
            for (int a = 0; a < 2; a++)
#pragma unroll
                for (int b = 0; b < 8; b++)
#pragma unroll
                    for (int k = 0; k < 4; k++) acc[a][b][k] = 0.f;
        }
    }
}

// ============================================================================
// proj kernel: 8 proj tiles x 8 rowblocks = 64 CTAs.  grid (8, 8)
// ============================================================================
__global__ __launch_bounds__(256, 2)
void proj_kernel()
{
    extern __shared__ char smem[];
    const int y = blockIdx.y;
    const int rowBase = blockIdx.x * 128;
    const uint4* W; uint4* C; int N, colBase;
    if (y < 4)      { W = pk_proj0; C = pk_h0; N = 512; colBase = y * 128; }
    else if (y < 6) { W = pk_proj1; C = pk_h1; N = 256; colBase = (y - 4) * 128; }
    else if (y == 6){ W = pk_proj2; C = pk_h2; N = 128; colBase = 0; }
    else            { W = pk_proj3; C = pk_h3; N = 64;  colBase = 0; }
    if (colBase + 128 <= N)
        gemm_stream<0, true>(pk_feat, W, C, N, 1024, rowBase, colBase,
                             -1, 0, smem);
    else
        gemm_stream<0, false>(pk_feat, W, C, N, 1024, rowBase, colBase,
                              -1, 0, smem);
}

// ============================================================================
// head kernel: 79 ytiles x 8 rowblocks.  grid (8, 79)   [side stream]
// ============================================================================
__global__ __launch_bounds__(256, 2)
void head_kernel()
{
    extern __shared__ char smem[];
    const int y = blockIdx.y;
    const int rowBase = blockIdx.x * 128;
    if (y < 78)
        gemm_stream<1, true>(pk_feat, pk_headW, nullptr, 10004, 1024,
                             rowBase, y * 128, 0, y, smem);
    else
        gemm_stream<1, false>(pk_feat, pk_headW, nullptr, 10004, 1024,
                              rowBase, y * 128, 0, y, smem);
}

// ============================================================================
// cluster kernel.  grid (8, 335)   [main stream, concurrent with head]
// ============================================================================
__global__ __launch_bounds__(256, 2)
void cluster_kernel()
{
    extern __shared__ char smem[];
    const int y = blockIdx.y;
    const int rowBase = blockIdx.x * 128;
    if (y < 79) {
        if (y < 78)
            gemm_stream<1, true>(pk_h0, pk_out0, nullptr, 10000, 512,
                                 rowBase, y * 128, 1, y, smem);
        else
            gemm_stream<1, false>(pk_h0, pk_out0, nullptr, 10000, 512,
                                  rowBase, y * 128, 1, y, smem);
    } else if (y < 236) {
        const int yt = y - 79;
        if (yt < 156)
            gemm_stream<1, true>(pk_h1, pk_out1, nullptr, 20000, 256,
                                 rowBase, yt * 128, 2, yt, smem);
        else
            gemm_stream<1, false>(pk_h1, pk_out1, nullptr, 20000, 256,
                                  rowBase, yt * 128, 2, yt, smem);
    } else if (y < 315) {
        const int y0 = (y - 236) * 4;
        const int cnt = (313 - y0 < 4) ? (313 - y0) : 4;
        gemm_resident<2>(pk_h2, pk_out2, 40000, rowBase, y0, cnt, 3, smem);
    } else {
        const int y0 = (y - 315) * 8;
        const int cnt = (157 - y0 < 8) ? (157 - y0) : 8;
        gemm_resident<1>(pk_h3, pk_out3, 20000, rowBase, y0, cnt, 4, smem);
    }
}

// ============================================================================
// pack_all: fp32 -> packed bf16 chunk images.  One block per 16KB image.
// One uint4 (16B) store per quad.
// ============================================================================
__global__ void pack_all(const float* s0, const float* s1, const float* s2,
                         const float* s3, const float* s4, const float* s5,
                         const float* s6, const float* s7, const float* s8,
                         const float* s9)
{
    int id = blockIdx.x;
    const float* src; uint4* dst; int K, N;
    if (id < 128)       { src = s0; dst = pk_feat;  K = 1024; N = 1024; }
    else if (id < 1392) { src = s1; dst = pk_headW; K = 1024; N = 10004; id -= 128; }
    else if (id < 2024) { src = s2; dst = pk_out0;  K = 512;  N = 10000; id -= 1392; }
    else if (id < 2652) { src = s3; dst = pk_out1;  K = 256;  N = 20000; id -= 2024; }
    else if (id < 3278) { src = s4; dst = pk_out2;  K = 128;  N = 40000; id -= 2652; }
    else if (id < 3435) { src = s5; dst = pk_out3;  K = 64;   N = 20000; id -= 3278; }
    else if (id < 3499) { src = s6; dst = pk_proj0; K = 1024; N = 512;  id -= 3435; }
    else if (id < 3531) { src = s7; dst = pk_proj1; K = 1024; N = 256;  id -= 3499; }
    else if (id < 3547) { src = s8; dst = pk_proj2; K = 1024; N = 128;  id -= 3531; }
    else                { src = s9; dst = pk_proj3; K = 1024; N = 64;   id -= 3547; }

    const int nch = K >> 6;
    const int t = id / nch, c = id - t * nch;
    char* img = (char*)(dst + (size_t)id * 1024);

    for (int u = threadIdx.x; u < 1024; u += 256) {
        const int r = u >> 3, q = u & 7;
        const int n = t * 128 + r;
        float4 va = make_float4(0.f, 0.f, 0.f, 0.f);
        float4 vb = make_float4(0.f, 0.f, 0.f, 0.f);
        if (n < N) {
            const float* p = src + (size_t)n * K + c * 64 + q * 8;
            va = *(const float4*)p;
            vb = *(const float4*)(p + 4);
        }
        const uint32_t boff = (uint32_t)(r * 128)
                            + (((uint32_t)(q * 16)) ^ ((uint32_t)((r & 7) << 4)));
        __nv_bfloat162 p0 = __floats2bfloat162_rn(va.x, va.y);
        __nv_bfloat162 p1 = __floats2bfloat162_rn(va.z, va.w);
        __nv_bfloat162 p2 = __floats2bfloat162_rn(vb.x, vb.y);
        __nv_bfloat162 p3 = __floats2bfloat162_rn(vb.z, vb.w);
        uint4 w;
        w.x = *(uint32_t*)&p0; w.y = *(uint32_t*)&p1;
        w.z = *(uint32_t*)&p2; w.w = *(uint32_t*)&p3;
        *(uint4*)(img + boff) = w;
    }
}

// ---------------------------------------------------------------- small kernels
__global__ void init_kernel(const void* tgt, const void* msk) {
    const int tid = threadIdx.x;
    if (tid < B_ROWS) { g_num[tid] = 0.f; g_den[tid] = 0.f; }
    if (tid == 0) {
        const int* ti = (const int*)tgt;
        int nz = 0;
        for (int j = 0; j < 128; j++) nz += (ti[2 * j + 1] != 0);
        g_flags[0] = (nz <= 8) ? 1 : 0;
        const unsigned int* mw = (const unsigned int*)msk;
        int looks_i32 = 1;
        for (int j = 0; j < 64; j++) if (mw[j] > 255u) looks_i32 = 0;
        g_flags[1] = looks_i32;
    }
}

__global__ void combine_kernel() {
    int row = blockIdx.x, mat = blockIdx.y, lane = threadIdx.x;
    int chunks = d_chunks[mat];
    const float* pm = g_pm + d_pbase[mat] + (size_t)row * chunks;
    const float* ps = g_ps + d_pbase[mat] + (size_t)row * chunks;
    float m = -INFINITY, s = 0.f;
    for (int c = lane; c < chunks; c += 32) {
        float mo = pm[c], so = ps[c];
        float M2 = fmaxf(m, mo);
        if (M2 == -INFINITY) { m = M2; s = 0.f; }
        else { s = s * __expf(m - M2) + so * __expf(mo - M2); m = M2; }
    }
    for (int o = 1; o < 32; o <<= 1) {
        float mo = __shfl_xor_sync(0xffffffffu, m, o);
        float so = __shfl_xor_sync(0xffffffffu, s, o);
        float M2 = fmaxf(m, mo);
        if (M2 == -INFINITY) { m = M2; s = 0.f; }
        else { s = s * __expf(m - M2) + so * __expf(mo - M2); m = M2; }
    }
    if (lane == 0) g_lse[mat * B_ROWS + row] = m + logf(s);
}

// warp per target; packed bf16 operands, fp32 accumulate
__global__ void loss_kernel(const float* __restrict__ discard,
                            const void* __restrict__ tgt,
                            const void* __restrict__ msk)
{
    int gwarp = (blockIdx.x * blockDim.x + threadIdx.x) >> 5;
    int lane  = threadIdx.x & 31;
    if (gwarp >= B_ROWS * 128) return;
    int b = gwarp >> 7;

    long long v;
    if (g_flags[0]) v = ((const long long*)tgt)[gwarp];
    else            v = (long long)((const int*)tgt)[gwarp];

    float mk;
    if (g_flags[1]) mk = (((const int*)msk)[gwarp] != 0) ? 1.f : 0.f;
    else            mk = (((const unsigned char*)msk)[gwarp] != 0) ? 1.f : 0.f;

    const uint4 *A, *W;
    int arow, wrow, Kd; float lse, extra;
    float hlse = g_lse[b];
    if (v < 10000) {
        A = pk_feat; arow = b; W = pk_headW; wrow = (int)v;
        Kd = 1024; lse = hlse; extra = 0.f;
    } else if (v < 20000) {
        A = pk_h0; arow = b; W = pk_out0; wrow = (int)v - 10000;
        Kd = 512; lse = g_lse[1 * B_ROWS + b]; extra = g_tail[b * 4 + 0] - hlse;
    } else if (v < 40000) {
        A = pk_h1; arow = b; W = pk_out1; wrow = (int)v - 20000;
        Kd = 256; lse = g_lse[2 * B_ROWS + b]; extra = g_tail[b * 4 + 1] - hlse;
    } else if (v < 80000) {
        A = pk_h2; arow = b; W = pk_out2; wrow = (int)v - 40000;
        Kd = 128; lse = g_lse[3 * B_ROWS + b]; extra = g_tail[b * 4 + 2] - hlse;
    } else {
        A = pk_h3; arow = b; W = pk_out3; wrow = (int)v - 80000;
        Kd = 64; lse = g_lse[4 * B_ROWS + b]; extra = g_tail[b * 4 + 3] - hlse;
    }

    const int nch = Kd >> 6;
    const uint4* abase = A + (size_t)(arow >> 7) * nch * 1024;
    const uint4* wbase = W + (size_t)(wrow >> 7) * nch * 1024;
    const int ar = arow & 127, wr = wrow & 127;
    const uint32_t q16x = (uint32_t)((lane & 7) * 16);
    const uint32_t aidx0 = ((uint32_t)(ar * 128)
                           + (q16x ^ ((uint32_t)((ar & 7) << 4)))) >> 4;
    const uint32_t widx0 = ((uint32_t)(wr * 128)
                           + (q16x ^ ((uint32_t)((wr & 7) << 4)))) >> 4;

    float dot = 0.f;
    for (int k = lane * 8; k < Kd; k += 256) {
        const int c = k >> 6;
        const uint4 av = abase[c * 1024 + aidx0];
        const uint4 wv = wbase[c * 1024 + widx0];
        const uint32_t aw[4] = {av.x, av.y, av.z, av.w};
        const uint32_t ww[4] = {wv.x, wv.y, wv.z, wv.w};
#pragma unroll
        for (int j = 0; j < 4; j++) {
            const float2 af2 = __bfloat1622float2(*(const __nv_bfloat162*)&aw[j]);
            const float2 wf2 = __bfloat1622float2(*(const __nv_bfloat162*)&ww[j]);
            dot += af2.x * wf2.x + af2.y * wf2.y;
        }
    }
#pragma unroll
    for (int o = 16; o >= 1; o >>= 1) dot += __shfl_xor_sync(0xffffffffu, dot, o);

    if (lane == 0) {
        float lp = dot - lse + extra;
        float wt = (1.f - discard[v]) * mk;
        atomicAdd(&g_num[b], -lp * wt);
        atomicAdd(&g_den[b], wt);
    }
}

__global__ void final_kernel(float* out) {
    __shared__ float red[256];
    float s = 0.f;
    for (int i = threadIdx.x; i < B_ROWS; i += 256) s += g_num[i] / g_den[i];
    red[threadIdx.x] = s;
    __syncthreads();
    for (int o = 128; o >= 1; o >>= 1) {
        if (threadIdx.x < o) red[threadIdx.x] += red[threadIdx.x + o];
        __syncthreads();
    }
    if (threadIdx.x == 0)
        out[0] = (float)((double)red[0] / (1024.0 + 1e-5));
}

// ============================================================================
extern "C" void kernel_launch(void* const* d_in, const int* in_sizes, int n_in,
                              void* d_out, int out_size)
{
    const float* feat    = (const float*)d_in[0];
    const float* headW   = (const float*)d_in[1];
    const float* proj0   = (const float*)d_in[2];
    const float* out0    = (const float*)d_in[3];
    const float* proj1   = (const float*)d_in[4];
    const float* out1    = (const float*)d_in[5];
    const float* proj2   = (const float*)d_in[6];
    const float* out2    = (const float*)d_in[7];
    const float* proj3   = (const float*)d_in[8];
    const float* out3    = (const float*)d_in[9];
    const float* discard = (const float*)d_in[10];
    const void*  tgt     = d_in[11];
    const void*  msk     = d_in[12];
    float* out = (float*)d_out;

    static cudaStream_t s2 = nullptr;
    static cudaEvent_t evFork = nullptr, evJoin = nullptr;
    if (s2 == nullptr) {
        cudaStreamCreateWithFlags(&s2, cudaStreamNonBlocking);
        cudaEventCreateWithFlags(&evFork, cudaEventDisableTiming);
        cudaEventCreateWithFlags(&evJoin, cudaEventDisableTiming);
        cudaFuncSetAttribute(proj_kernel,
                             cudaFuncAttributeMaxDynamicSharedMemorySize, SMEM_SZ);
        cudaFuncSetAttribute(head_kernel,
                             cudaFuncAttributeMaxDynamicSharedMemorySize, SMEM_SZ);
        cudaFuncSetAttribute(cluster_kernel,
                             cudaFuncAttributeMaxDynamicSharedMemorySize, SMEM_SZ);
    }

    init_kernel<<<1, 1024>>>(tgt, msk);
    pack_all<<<3563, 256>>>(feat, headW, out0, out1, out2, out3,
                            proj0, proj1, proj2, proj3);
    proj_kernel<<<dim3(8, 8), 256, SMEM_SZ>>>();

    // fork: head on side stream, clusters on main stream (both after proj)
    cudaEventRecord(evFork, 0);
    cudaStreamWaitEvent(s2, evFork, 0);
    head_kernel<<<dim3(8, 79), 256, SMEM_SZ, s2>>>();
    cluster_kernel<<<dim3(8, 335), 256, SMEM_SZ>>>();
    cudaEventRecord(evJoin, s2);
    cudaStreamWaitEvent(0, evJoin, 0);

    combine_kernel<<<dim3(1024, 5), 32>>>();
    loss_kernel<<<16384, 256>>>(discard, tgt, msk);
    final_kernel<<<1, 256>>>(out);
}

// round 17
// speedup vs baseline: 1.1382x; 1.0005x over previous
#include <cuda_runtime.h>
#include <cuda_bf16.h>
#include <cstdint>
#include <math.h>

// ============================================================================
// AdaptiveLoss, bf16 mma.sync. Round 17:
//  - R16 packed-image + cp.async.bulk GEMM core (arithmetic unchanged)
//  - c1 (K=256) moves to A-resident path (NCH=4, groups of 2)
//  - pack split: pack_out runs on its own stream, overlapped with the
//    main chain; head overlaps proj+cluster on a second stream
//  - combine_kernel at 8 warps/block
// ============================================================================

#define B_ROWS 1024
#define IMG    16384u           // one chunk image: 128 rows x 128 B
#define STG    32768u           // stream stage: A img + B img
#define MB_OFF 114688u
#define SMEM_SZ 114752u

// 64-col partial chunks (2 per 128-col ytile)
__device__ const int d_chunks[5] = {158, 158, 314, 626, 314};
__device__ const int d_pbase[5]  = {0, 161792, 323584, 645120, 1286144};
#define PM_TOTAL 1607680

__device__ float g_pm[PM_TOTAL];
__device__ float g_ps[PM_TOTAL];
__device__ float g_lse[5 * B_ROWS];
__device__ float g_tail[B_ROWS * 4];
__device__ float g_num[B_ROWS];
__device__ float g_den[B_ROWS];
__device__ int   g_flags[2];

// packed operand storage (uint4 = 16B units; 1024 units per image)
__device__ uint4 pk_feat [131072];
__device__ uint4 pk_headW[1294336];
__device__ uint4 pk_out0 [647168];
__device__ uint4 pk_out1 [643072];
__device__ uint4 pk_out2 [641024];
__device__ uint4 pk_out3 [160768];
__device__ uint4 pk_proj0[65536];
__device__ uint4 pk_proj1[32768];
__device__ uint4 pk_proj2[16384];
__device__ uint4 pk_proj3[16384];
__device__ uint4 pk_h0   [65536];
__device__ uint4 pk_h1   [32768];
__device__ uint4 pk_h2   [16384];
__device__ uint4 pk_h3   [8192];

// ---------------------------------------------------------------- PTX helpers
__device__ __forceinline__ uint32_t smem_u32(const void* p) {
    uint32_t a;
    asm("{ .reg .u64 t; cvta.to.shared.u64 t, %1; cvt.u32.u64 %0, t; }"
        : "=r"(a) : "l"(p));
    return a;
}
#define MBAR_INIT(a, c) \
    asm volatile("mbarrier.init.shared.b64 [%0], %1;" :: "r"(a), "r"(c) : "memory")
#define MBAR_EXPECT(a, b) \
    asm volatile("mbarrier.arrive.expect_tx.shared.b64 _, [%0], %1;" \
                 :: "r"(a), "r"(b) : "memory")
#define MBAR_WAIT(addr, par) do {                                            \
    uint32_t _m = (addr), _p = (par), _d;                                    \
    do {                                                                     \
        asm volatile("{\n\t.reg .pred p;\n\t"                                \
            "mbarrier.try_wait.parity.shared.b64 p, [%1], %2, 0x989680;\n\t" \
            "selp.b32 %0, 1, 0, p;\n\t}" : "=r"(_d) : "r"(_m), "r"(_p) : "memory"); \
    } while (!_d);                                                           \
} while (0)
__device__ __forceinline__ void bulk_cp(uint32_t dst, const void* src,
                                        uint32_t bytes, uint32_t mbar) {
    asm volatile(
        "cp.async.bulk.shared::cta.global.mbarrier::complete_tx::bytes "
        "[%0], [%1], %2, [%3];"
        :: "r"(dst), "l"(src), "r"(bytes), "r"(mbar) : "memory");
}
__device__ __forceinline__ void ldsm_x4(uint32_t* r, uint32_t addr) {
    asm volatile("ldmatrix.sync.aligned.m8n8.x4.shared.b16 {%0,%1,%2,%3}, [%4];"
                 : "=r"(r[0]), "=r"(r[1]), "=r"(r[2]), "=r"(r[3]) : "r"(addr));
}
__device__ __forceinline__ void mma_bf16(float* c, const uint32_t* a,
                                         const uint32_t* b) {
    asm volatile(
        "mma.sync.aligned.m16n8k16.row.col.f32.bf16.bf16.f32 "
        "{%0,%1,%2,%3}, {%4,%5,%6,%7}, {%8,%9}, {%0,%1,%2,%3};"
        : "+f"(c[0]), "+f"(c[1]), "+f"(c[2]), "+f"(c[3])
        : "r"(a[0]), "r"(a[1]), "r"(a[2]), "r"(a[3]), "r"(b[0]), "r"(b[1]));
}

// ---- 32x64 warp-tile compute over one 64-K chunk (packed layout) -----------
__device__ __forceinline__ void mma_tile(uint32_t aB, uint32_t bB,
    uint32_t aRow0, uint32_t bRow0, uint32_t xm,
    uint32_t aqs, uint32_t bqs, float (&acc)[2][8][4])
{
#pragma unroll
    for (int ks = 0; ks < 4; ks++) {
        uint32_t af[2][4], bf4[4][4];
        const uint32_t aoff = ((uint32_t)(ks * 32) + aqs) ^ xm;
        const uint32_t boff = ((uint32_t)(ks * 32) + bqs) ^ xm;
#pragma unroll
        for (int mt = 0; mt < 2; mt++)
            ldsm_x4(af[mt], aB + aRow0 + mt * 2048 + aoff);
#pragma unroll
        for (int p = 0; p < 4; p++)
            ldsm_x4(bf4[p], bB + bRow0 + p * 2048 + boff);
#pragma unroll
        for (int mt = 0; mt < 2; mt++)
#pragma unroll
            for (int nt = 0; nt < 8; nt++)
                mma_bf16(acc[mt][nt], af[mt], &bf4[nt >> 1][(nt & 1) * 2]);
    }
}

// ---- de-staged online-LSE epilogue -----------------------------------------
template <bool FULL>
__device__ __forceinline__ void epi_lse(float (&acc)[2][8][4], int N,
    int rowBase, int colBase, int sel, int ytile,
    int warpM, int warpN, int lane)
{
    const int chunks = d_chunks[sel];
    const int cidx = ytile * 2 + warpN;
#pragma unroll
    for (int mt = 0; mt < 2; mt++)
#pragma unroll
        for (int hf = 0; hf < 2; hf++) {
            const int rg = rowBase + warpM * 32 + mt * 16 + (lane >> 2) + hf * 8;
            float m = -INFINITY, s = 0.f;
            if (FULL) {
#pragma unroll
                for (int nt = 0; nt < 8; nt++)
#pragma unroll
                    for (int b2 = 0; b2 < 2; b2++)
                        m = fmaxf(m, acc[mt][nt][hf * 2 + b2]);
#pragma unroll
                for (int nt = 0; nt < 8; nt++)
#pragma unroll
                    for (int b2 = 0; b2 < 2; b2++)
                        s += __expf(acc[mt][nt][hf * 2 + b2] - m);
            } else {
#pragma unroll
                for (int nt = 0; nt < 8; nt++)
#pragma unroll
                    for (int b2 = 0; b2 < 2; b2++) {
                        const int cc = colBase + warpN * 64 + nt * 8
                                     + (lane & 3) * 2 + b2;
                        if (cc < N) m = fmaxf(m, acc[mt][nt][hf * 2 + b2]);
                    }
                if (m > -INFINITY) {
#pragma unroll
                    for (int nt = 0; nt < 8; nt++)
#pragma unroll
                        for (int b2 = 0; b2 < 2; b2++) {
                            const int cc = colBase + warpN * 64 + nt * 8
                                         + (lane & 3) * 2 + b2;
                            if (cc < N) {
                                const float v = acc[mt][nt][hf * 2 + b2];
                                s += __expf(v - m);
                                if (sel == 0 && cc >= 10000)
                                    g_tail[rg * 4 + (cc - 10000)] = v;
                            }
                        }
                }
            }
#pragma unroll
            for (int o = 1; o <= 2; o <<= 1) {
                const float mo = __shfl_xor_sync(0xffffffffu, m, o);
                const float so = __shfl_xor_sync(0xffffffffu, s, o);
                const float M2 = fmaxf(m, mo);
                if (M2 == -INFINITY) { m = M2; s = 0.f; }
                else { s = s * __expf(m - M2) + so * __expf(mo - M2); m = M2; }
            }
            if ((lane & 3) == 0) {
                const size_t o = d_pbase[sel] + (size_t)rg * chunks + cidx;
                g_pm[o] = m; g_ps[o] = s;
            }
        }
}

// ============================================================================
// Streaming GEMM over packed images: one bulk copy pair per chunk.
// ============================================================================
template <int MODE, bool FULL>
__device__ __forceinline__ void gemm_stream(
    const uint4* __restrict__ Apk, const uint4* __restrict__ Bpk,
    uint4* __restrict__ Cpk, int N, int K,
    int rowBase, int colBase, int sel, int ytile, char* smem)
{
    const uint32_t sb = smem_u32(smem);
    const int tid = threadIdx.x, lane = tid & 31, wid = tid >> 5;
    const int warpM = wid & 3, warpN = wid >> 2;
    const int nch = K >> 6;

    const uint4* Aimg = Apk + (size_t)(rowBase >> 7) * nch * 1024;
    const uint4* Bimg = Bpk + (size_t)(colBase >> 7) * nch * 1024;

    if (tid == 0) {
        MBAR_INIT(sb + MB_OFF + 0, 1);
        MBAR_INIT(sb + MB_OFF + 8, 1);
        MBAR_INIT(sb + MB_OFF + 16, 1);
    }
    __syncthreads();
    if (tid == 0) {
        MBAR_EXPECT(sb + MB_OFF, 2 * IMG);
        bulk_cp(sb, Aimg, IMG, sb + MB_OFF);
        bulk_cp(sb + IMG, Bimg, IMG, sb + MB_OFF);
        MBAR_EXPECT(sb + MB_OFF + 8, 2 * IMG);
        bulk_cp(sb + STG, Aimg + 1024, IMG, sb + MB_OFF + 8);
        bulk_cp(sb + STG + IMG, Bimg + 1024, IMG, sb + MB_OFF + 8);
    }

    float acc[2][8][4];
#pragma unroll
    for (int i = 0; i < 2; i++)
#pragma unroll
        for (int j = 0; j < 8; j++)
#pragma unroll
            for (int k = 0; k < 4; k++) acc[i][j][k] = 0.f;

    const uint32_t xm = (uint32_t)((lane & 7) << 4);
    const uint32_t aRow0 =
        (uint32_t)((warpM * 32 + ((lane >> 3) & 1) * 8 + (lane & 7)) * 128);
    const uint32_t bRow0 =
        (uint32_t)((warpN * 64 + ((lane >> 4) & 1) * 8 + (lane & 7)) * 128);
    const uint32_t aqs = (uint32_t)((lane >> 4) * 16);
    const uint32_t bqs = (uint32_t)(((lane >> 3) & 1) * 16);

    for (int c = 0; c < nch; c++) {
        const int buf = c % 3;
        MBAR_WAIT(sb + MB_OFF + buf * 8, (c / 3) & 1);
        __syncthreads();
        if (tid == 0 && c + 2 < nch) {
            const int nb = (c + 2) % 3;
            MBAR_EXPECT(sb + MB_OFF + nb * 8, 2 * IMG);
            bulk_cp(sb + nb * STG, Aimg + (c + 2) * 1024, IMG,
                    sb + MB_OFF + nb * 8);
            bulk_cp(sb + nb * STG + IMG, Bimg + (c + 2) * 1024, IMG,
                    sb + MB_OFF + nb * 8);
        }
        mma_tile(sb + buf * STG, sb + buf * STG + IMG,
                 aRow0, bRow0, xm, aqs, bqs, acc);
    }

    if (MODE == 0) {
        const int nchC = N >> 6;
        char* base = (char*)Cpk + (size_t)(rowBase >> 7) * nchC * IMG;
#pragma unroll
        for (int mt = 0; mt < 2; mt++)
#pragma unroll
            for (int nt = 0; nt < 8; nt++)
#pragma unroll
                for (int rg = 0; rg < 4; rg++) {
                    const int r = warpM * 32 + mt * 16 + (lane >> 2)
                                + (rg >> 1) * 8;
                    const int cc = colBase + warpN * 64 + nt * 8
                                 + (lane & 3) * 2 + (rg & 1);
                    if (cc < N) {
                        const size_t off = (size_t)(cc >> 6) * IMG
                            + (uint32_t)(r * 128)
                            + ((((cc >> 3) & 7) * 16) ^ ((r & 7) << 4))
                            + (cc & 7) * 2;
                        *(__nv_bfloat16*)(base + off) =
                            __float2bfloat16(acc[mt][nt][rg]);
                    }
                }
    } else {
        epi_lse<FULL>(acc, N, rowBase, colBase, sel, ytile, warpM, warpN, lane);
    }
}

// ============================================================================
// A-resident GEMM (K<=256): A images resident; streams B images for `cnt`
// consecutive 128-col ytiles.  B buffers at NCH*IMG + buf*IMG.
// ============================================================================
template <int NCH>
__device__ __forceinline__ void gemm_resident(
    const uint4* __restrict__ Apk, const uint4* __restrict__ Bpk,
    int N, int rowBase, int y0, int cnt, int sel, char* smem)
{
    const uint32_t sb = smem_u32(smem);
    const int tid = threadIdx.x, lane = tid & 31, wid = tid >> 5;
    const int warpM = wid & 3, warpN = wid >> 2;
    const uint32_t bbase = NCH * IMG;

    const uint4* Aimg = Apk + (size_t)(rowBase >> 7) * NCH * 1024;

    if (tid == 0) {
        MBAR_INIT(sb + MB_OFF + 0, 1);
        MBAR_INIT(sb + MB_OFF + 8, 1);
        MBAR_INIT(sb + MB_OFF + 16, 1);
    }
    __syncthreads();
    const int total = cnt * NCH;
    if (tid == 0) {
        MBAR_EXPECT(sb + MB_OFF, (NCH + 1) * IMG);
#pragma unroll
        for (int c = 0; c < NCH; c++)
            bulk_cp(sb + c * IMG, Aimg + c * 1024, IMG, sb + MB_OFF);
        bulk_cp(sb + bbase, Bpk + (size_t)(y0 * NCH) * 1024, IMG, sb + MB_OFF);
        if (total > 1) {
            MBAR_EXPECT(sb + MB_OFF + 8, IMG);
            bulk_cp(sb + bbase + IMG, Bpk + (size_t)(y0 * NCH + 1) * 1024,
                    IMG, sb + MB_OFF + 8);
        }
    }

    float acc[2][8][4];
#pragma unroll
    for (int i = 0; i < 2; i++)
#pragma unroll
        for (int j = 0; j < 8; j++)
#pragma unroll
            for (int k = 0; k < 4; k++) acc[i][j][k] = 0.f;

    const uint32_t xm = (uint32_t)((lane & 7) << 4);
    const uint32_t aRow0 =
        (uint32_t)((warpM * 32 + ((lane >> 3) & 1) * 8 + (lane & 7)) * 128);
    const uint32_t bRow0 =
        (uint32_t)((warpN * 64 + ((lane >> 4) & 1) * 8 + (lane & 7)) * 128);
    const uint32_t aqs = (uint32_t)((lane >> 4) * 16);
    const uint32_t bqs = (uint32_t)(((lane >> 3) & 1) * 16);

    for (int i = 0; i < total; i++) {
        const int t = i / NCH, c = i - t * NCH;
        const int buf = i % 3;
        MBAR_WAIT(sb + MB_OFF + buf * 8, (i / 3) & 1);
        __syncthreads();
        if (tid == 0 && i + 2 < total) {
            const int nb = (i + 2) % 3;
            MBAR_EXPECT(sb + MB_OFF + nb * 8, IMG);
            bulk_cp(sb + bbase + nb * IMG,
                    Bpk + (size_t)(y0 * NCH + i + 2) * 1024, IMG,
                    sb + MB_OFF + nb * 8);
        }
        mma_tile(sb + c * IMG, sb + bbase + buf * IMG,
                 aRow0, bRow0, xm, aqs, bqs, acc);
        if (c == NCH - 1) {
            const int colBase = (y0 + t) * 128;
            if (colBase + 128 <= N)
                epi_lse<true>(acc, N, rowBase, colBase, sel, y0 + t,
                              warpM, warpN, lane);
            else
                epi_lse<false>(acc, N, rowBase, colBase, sel, y0 + t,
                               warpM, warpN, lane);
#pragma unroll
            for (int a = 0; a < 2; a++)
#pragma unroll
                for (int b = 0; b < 8; b++)
#pragma unroll
                    for (int k = 0; k < 4; k++) acc[a][b][k] = 0.f;
        }
    }
}

// ============================================================================
// proj kernel: grid (8, 8)
// ============================================================================
__global__ __launch_bounds__(256, 2)
void proj_kernel()
{
    extern __shared__ char smem[];
    const int y = blockIdx.y;
    const int rowBase = blockIdx.x * 128;
    const uint4* W; uint4* C; int N, colBase;
    if (y < 4)      { W = pk_proj0; C = pk_h0; N = 512; colBase = y * 128; }
    else if (y < 6) { W = pk_proj1; C = pk_h1; N = 256; colBase = (y - 4) * 128; }
    else if (y == 6){ W = pk_proj2; C = pk_h2; N = 128; colBase = 0; }
    else            { W = pk_proj3; C = pk_h3; N = 64;  colBase = 0; }
    if (colBase + 128 <= N)
        gemm_stream<0, true>(pk_feat, W, C, N, 1024, rowBase, colBase,
                             -1, 0, smem);
    else
        gemm_stream<0, false>(pk_feat, W, C, N, 1024, rowBase, colBase,
                              -1, 0, smem);
}

// ============================================================================
// head kernel: grid (8, 79)   [side stream]
// ============================================================================
__global__ __launch_bounds__(256, 2)
void head_kernel()
{
    extern __shared__ char smem[];
    const int y = blockIdx.y;
    const int rowBase = blockIdx.x * 128;
    if (y < 78)
        gemm_stream<1, true>(pk_feat, pk_headW, nullptr, 10004, 1024,
                             rowBase, y * 128, 0, y, smem);
    else
        gemm_stream<1, false>(pk_feat, pk_headW, nullptr, 10004, 1024,
                              rowBase, y * 128, 0, y, smem);
}

// ============================================================================
// cluster kernel.  grid (8, 257):
//   0..78    c0 K=512 stream    (79 ytiles)
//   79..157  c1 K=256 resident<4> groups of 2 (79 groups, 157 ytiles)
//   158..236 c2 K=128 resident<2> groups of 4 (79 groups, 313 ytiles)
//   237..256 c3 K=64  resident<1> groups of 8 (20 groups, 157 ytiles)
// ============================================================================
__global__ __launch_bounds__(256, 2)
void cluster_kernel()
{
    extern __shared__ char smem[];
    const int y = blockIdx.y;
    const int rowBase = blockIdx.x * 128;
    if (y < 79) {
        if (y < 78)
            gemm_stream<1, true>(pk_h0, pk_out0, nullptr, 10000, 512,
                                 rowBase, y * 128, 1, y, smem);
        else
            gemm_stream<1, false>(pk_h0, pk_out0, nullptr, 10000, 512,
                                  rowBase, y * 128, 1, y, smem);
    } else if (y < 158) {
        const int y0 = (y - 79) * 2;
        const int cnt = (157 - y0 < 2) ? (157 - y0) : 2;
        gemm_resident<4>(pk_h1, pk_out1, 20000, rowBase, y0, cnt, 2, smem);
    } else if (y < 237) {
        const int y0 = (y - 158) * 4;
        const int cnt = (313 - y0 < 4) ? (313 - y0) : 4;
        gemm_resident<2>(pk_h2, pk_out2, 40000, rowBase, y0, cnt, 3, smem);
    } else {
        const int y0 = (y - 237) * 8;
        const int cnt = (157 - y0 < 8) ? (157 - y0) : 8;
        gemm_resident<1>(pk_h3, pk_out3, 20000, rowBase, y0, cnt, 4, smem);
    }
}

// ============================================================================
// packing: one block per 16KB image; one uint4 store per quad.
// ============================================================================
__device__ __forceinline__ void pack_img(const float* src, uint4* dst,
                                         int K, int N, int id)
{
    const int nch = K >> 6;
    const int t = id / nch, c = id - t * nch;
    char* img = (char*)(dst + (size_t)id * 1024);
    for (int u = threadIdx.x; u < 1024; u += 256) {
        const int r = u >> 3, q = u & 7;
        const int n = t * 128 + r;
        float4 va = make_float4(0.f, 0.f, 0.f, 0.f);
        float4 vb = make_float4(0.f, 0.f, 0.f, 0.f);
        if (n < N) {
            const float* p = src + (size_t)n * K + c * 64 + q * 8;
            va = *(const float4*)p;
            vb = *(const float4*)(p + 4);
        }
        const uint32_t boff = (uint32_t)(r * 128)
                            + (((uint32_t)(q * 16)) ^ ((uint32_t)((r & 7) << 4)));
        __nv_bfloat162 p0 = __floats2bfloat162_rn(va.x, va.y);
        __nv_bfloat162 p1 = __floats2bfloat162_rn(va.z, va.w);
        __nv_bfloat162 p2 = __floats2bfloat162_rn(vb.x, vb.y);
        __nv_bfloat162 p3 = __floats2bfloat162_rn(vb.z, vb.w);
        uint4 w;
        w.x = *(uint32_t*)&p0; w.y = *(uint32_t*)&p1;
        w.z = *(uint32_t*)&p2; w.w = *(uint32_t*)&p3;
        *(uint4*)(img + boff) = w;
    }
}

// pack_main: feat(128) headW(1264) proj0(64) proj1(32) proj2(16) proj3(16)
__global__ void pack_main(const float* feat, const float* headW,
                          const float* p0, const float* p1,
                          const float* p2, const float* p3)
{
    int id = blockIdx.x;
    if (id < 128)       pack_img(feat,  pk_feat,  1024, 1024,  id);
    else if (id < 1392) pack_img(headW, pk_headW, 1024, 10004, id - 128);
    else if (id < 1456) pack_img(p0,    pk_proj0, 1024, 512,   id - 1392);
    else if (id < 1488) pack_img(p1,    pk_proj1, 1024, 256,   id - 1456);
    else if (id < 1504) pack_img(p2,    pk_proj2, 1024, 128,   id - 1488);
    else                pack_img(p3,    pk_proj3, 1024, 64,    id - 1504);
}

// pack_out: out0(632) out1(628) out2(626) out3(157)
__global__ void pack_out(const float* o0, const float* o1,
                         const float* o2, const float* o3)
{
    int id = blockIdx.x;
    if (id < 632)       pack_img(o0, pk_out0, 512, 10000, id);
    else if (id < 1260) pack_img(o1, pk_out1, 256, 20000, id - 632);
    else if (id < 1886) pack_img(o2, pk_out2, 128, 40000, id - 1260);
    else                pack_img(o3, pk_out3, 64,  20000, id - 1886);
}

// ---------------------------------------------------------------- small kernels
__global__ void init_kernel(const void* tgt, const void* msk) {
    const int tid = threadIdx.x;
    if (tid < B_ROWS) { g_num[tid] = 0.f; g_den[tid] = 0.f; }
    if (tid == 0) {
        const int* ti = (const int*)tgt;
        int nz = 0;
        for (int j = 0; j < 128; j++) nz += (ti[2 * j + 1] != 0);
        g_flags[0] = (nz <= 8) ? 1 : 0;
        const unsigned int* mw = (const unsigned int*)msk;
        int looks_i32 = 1;
        for (int j = 0; j < 64; j++) if (mw[j] > 255u) looks_i32 = 0;
        g_flags[1] = looks_i32;
    }
}

// grid 640, block 256: warp w handles pair = blockIdx*8 + w
__global__ void combine_kernel() {
    const int w = threadIdx.x >> 5, lane = threadIdx.x & 31;
    const int pair = blockIdx.x * 8 + w;
    const int mat = pair >> 10, row = pair & 1023;
    const int chunks = d_chunks[mat];
    const float* pm = g_pm + d_pbase[mat] + (size_t)row * chunks;
    const float* ps = g_ps + d_pbase[mat] + (size_t)row * chunks;
    float m = -INFINITY, s = 0.f;
    for (int c = lane; c < chunks; c += 32) {
        float mo = pm[c], so = ps[c];
        float M2 = fmaxf(m, mo);
        if (M2 == -INFINITY) { m = M2; s = 0.f; }
        else { s = s * __expf(m - M2) + so * __expf(mo - M2); m = M2; }
    }
    for (int o = 1; o < 32; o <<= 1) {
        float mo = __shfl_xor_sync(0xffffffffu, m, o);
        float so = __shfl_xor_sync(0xffffffffu, s, o);
        float M2 = fmaxf(m, mo);
        if (M2 == -INFINITY) { m = M2; s = 0.f; }
        else { s = s * __expf(m - M2) + so * __expf(mo - M2); m = M2; }
    }
    if (lane == 0) g_lse[mat * B_ROWS + row] = m + logf(s);
}

// warp per target; packed bf16 operands, fp32 accumulate
__global__ void loss_kernel(const float* __restrict__ discard,
                            const void* __restrict__ tgt,
                            const void* __restrict__ msk)
{
    int gwarp = (blockIdx.x * blockDim.x + threadIdx.x) >> 5;
    int lane  = threadIdx.x & 31;
    if (gwarp >= B_ROWS * 128) return;
    int b = gwarp >> 7;

    long long v;
    if (g_flags[0]) v = ((const long long*)tgt)[gwarp];
    else            v = (long long)((const int*)tgt)[gwarp];

    float mk;
    if (g_flags[1]) mk = (((const int*)msk)[gwarp] != 0) ? 1.f : 0.f;
    else            mk = (((const unsigned char*)msk)[gwarp] != 0) ? 1.f : 0.f;

    const uint4 *A, *W;
    int arow, wrow, Kd; float lse, extra;
    float hlse = g_lse[b];
    if (v < 10000) {
        A = pk_feat; arow = b; W = pk_headW; wrow = (int)v;
        Kd = 1024; lse = hlse; extra = 0.f;
    } else if (v < 20000) {
        A = pk_h0; arow = b; W = pk_out0; wrow = (int)v - 10000;
        Kd = 512; lse = g_lse[1 * B_ROWS + b]; extra = g_tail[b * 4 + 0] - hlse;
    } else if (v < 40000) {
        A = pk_h1; arow = b; W = pk_out1; wrow = (int)v - 20000;
        Kd = 256; lse = g_lse[2 * B_ROWS + b]; extra = g_tail[b * 4 + 1] - hlse;
    } else if (v < 80000) {
        A = pk_h2; arow = b; W = pk_out2; wrow = (int)v - 40000;
        Kd = 128; lse = g_lse[3 * B_ROWS + b]; extra = g_tail[b * 4 + 2] - hlse;
    } else {
        A = pk_h3; arow = b; W = pk_out3; wrow = (int)v - 80000;
        Kd = 64; lse = g_lse[4 * B_ROWS + b]; extra = g_tail[b * 4 + 3] - hlse;
    }

    const int nch = Kd >> 6;
    const uint4* abase = A + (size_t)(arow >> 7) * nch * 1024;
    const uint4* wbase = W + (size_t)(wrow >> 7) * nch * 1024;
    const int ar = arow & 127, wr = wrow & 127;
    const uint32_t q16x = (uint32_t)((lane & 7) * 16);
    const uint32_t aidx0 = ((uint32_t)(ar * 128)
                           + (q16x ^ ((uint32_t)((ar & 7) << 4)))) >> 4;
    const uint32_t widx0 = ((uint32_t)(wr * 128)
                           + (q16x ^ ((uint32_t)((wr & 7) << 4)))) >> 4;

    float dot = 0.f;
    for (int k = lane * 8; k < Kd; k += 256) {
        const int c = k >> 6;
        const uint4 av = abase[c * 1024 + aidx0];
        const uint4 wv = wbase[c * 1024 + widx0];
        const uint32_t aw[4] = {av.x, av.y, av.z, av.w};
        const uint32_t ww[4] = {wv.x, wv.y, wv.z, wv.w};
#pragma unroll
        for (int j = 0; j < 4; j++) {
            const float2 af2 = __bfloat1622float2(*(const __nv_bfloat162*)&aw[j]);
            const float2 wf2 = __bfloat1622float2(*(const __nv_bfloat162*)&ww[j]);
            dot += af2.x * wf2.x + af2.y * wf2.y;
        }
    }
#pragma unroll
    for (int o = 16; o >= 1; o >>= 1) dot += __shfl_xor_sync(0xffffffffu, dot, o);

    if (lane == 0) {
        float lp = dot - lse + extra;
        float wt = (1.f - discard[v]) * mk;
        atomicAdd(&g_num[b], -lp * wt);
        atomicAdd(&g_den[b], wt);
    }
}

__global__ void final_kernel(float* out) {
    __shared__ float red[256];
    float s = 0.f;
    for (int i = threadIdx.x; i < B_ROWS; i += 256) s += g_num[i] / g_den[i];
    red[threadIdx.x] = s;
    __syncthreads();
    for (int o = 128; o >= 1; o >>= 1) {
        if (threadIdx.x < o) red[threadIdx.x] += red[threadIdx.x + o];
        __syncthreads();
    }
    if (threadIdx.x == 0)
        out[0] = (float)((double)red[0] / (1024.0 + 1e-5));
}

// ============================================================================
extern "C" void kernel_launch(void* const* d_in, const int* in_sizes, int n_in,
                              void* d_out, int out_size)
{
    const float* feat    = (const float*)d_in[0];
    const float* headW   = (const float*)d_in[1];
    const float* proj0   = (const float*)d_in[2];
    const float* out0    = (const float*)d_in[3];
    const float* proj1   = (const float*)d_in[4];
    const float* out1    = (const float*)d_in[5];
    const float* proj2   = (const float*)d_in[6];
    const float* out2    = (const float*)d_in[7];
    const float* proj3   = (const float*)d_in[8];
    const float* out3    = (const float*)d_in[9];
    const float* discard = (const float*)d_in[10];
    const void*  tgt     = d_in[11];
    const void*  msk     = d_in[12];
    float* out = (float*)d_out;

    static cudaStream_t s2 = nullptr, s3 = nullptr;
    static cudaEvent_t evFork = nullptr, evJoin = nullptr;
    static cudaEvent_t evStart = nullptr, evOut = nullptr;
    if (s2 == nullptr) {
        cudaStreamCreateWithFlags(&s2, cudaStreamNonBlocking);
        cudaStreamCreateWithFlags(&s3, cudaStreamNonBlocking);
        cudaEventCreateWithFlags(&evFork,  cudaEventDisableTiming);
        cudaEventCreateWithFlags(&evJoin,  cudaEventDisableTiming);
        cudaEventCreateWithFlags(&evStart, cudaEventDisableTiming);
        cudaEventCreateWithFlags(&evOut,   cudaEventDisableTiming);
        cudaFuncSetAttribute(proj_kernel,
                             cudaFuncAttributeMaxDynamicSharedMemorySize, SMEM_SZ);
        cudaFuncSetAttribute(head_kernel,
                             cudaFuncAttributeMaxDynamicSharedMemorySize, SMEM_SZ);
        cudaFuncSetAttribute(cluster_kernel,
                             cudaFuncAttributeMaxDynamicSharedMemorySize, SMEM_SZ);
    }

    init_kernel<<<1, 1024>>>(tgt, msk);

    // s3: pack cluster weights (independent of everything on main)
    cudaEventRecord(evStart, 0);
    cudaStreamWaitEvent(s3, evStart, 0);
    pack_out<<<2043, 256, 0, s3>>>(out0, out1, out2, out3);
    cudaEventRecord(evOut, s3);

    // main: pack head/proj operands, then proj
    pack_main<<<1520, 256>>>(feat, headW, proj0, proj1, proj2, proj3);

    // s2: head runs as soon as pack_main is done (overlaps proj + clusters)
    cudaEventRecord(evFork, 0);
    cudaStreamWaitEvent(s2, evFork, 0);
    head_kernel<<<dim3(8, 79), 256, SMEM_SZ, s2>>>();

    proj_kernel<<<dim3(8, 8), 256, SMEM_SZ>>>();

    // clusters need proj (main-order) + pack_out (event)
    cudaStreamWaitEvent(0, evOut, 0);
    cluster_kernel<<<dim3(8, 257), 256, SMEM_SZ>>>();

    // join head before combine
    cudaEventRecord(evJoin, s2);
    cudaStreamWaitEvent(0, evJoin, 0);

    combine_kernel<<<640, 256>>>();
    loss_kernel<<<16384, 256>>>(discard, tgt, msk);
    final_kernel<<<1, 256>>>(out);
}